// round 7
// baseline (speedup 1.0000x reference)
#include <cuda_runtime.h>
#include <cuda_fp16.h>
#include <cstdint>
#include <math.h>

#define NN   50000
#define EE   400000
#define IND  256
#define HIDD 128
#define TT   3
#define RR   4
#define HH   8
#define DKK  16
#define NP   50432          // 394 blocks * 128
#define NTILE 394
#define NCHUNKS 66          // 6 adapt + 2*(3 q + 24 composite + 3 att)

// ---------------- scratch (static device globals) -----------------------------
__device__ float d_h0[NP*HIDD];
__device__ float d_h1[NP*HIDD];
__device__ float d_agg[NP*HIDD];
__device__ __half d_qh[NP*HIDD];
__device__ __half d_kvrel[(size_t)NP*RR*256];   // [p*4+r][0:128]=krel*pri/4, [128:256]=vrel
__device__ __half d_wpack[NCHUNKS*16384];
__device__ float  d_bcomp[NCHUNKS*128];
__device__ int   d_deg[NN];
__device__ int   d_off[NN+1];
__device__ int   d_cursor[NN];
__device__ int   d_epack[EE];
__device__ int   d_bsum[256];
__device__ int   d_bpre[256];
__device__ int   d_tcnt[TT];
__device__ int   d_topad[TT+1];
__device__ int   d_tcur[TT];
__device__ int   d_nperm[NP];
__device__ int   d_iperm[NN];

// ---------------- helpers -------------------------------------------------------
__device__ __forceinline__ uint32_t smem_u32(const void* p) {
    uint32_t a;
    asm("{ .reg .u64 t; cvta.to.shared.u64 t, %1; cvt.u32.u64 %0, t; }" : "=r"(a) : "l"(p));
    return a;
}
__device__ __forceinline__ void ldmatrix_x4(uint32_t* r, uint32_t addr) {
    asm volatile("ldmatrix.sync.aligned.m8n8.x4.shared.b16 {%0,%1,%2,%3}, [%4];"
                 : "=r"(r[0]), "=r"(r[1]), "=r"(r[2]), "=r"(r[3]) : "r"(addr));
}
__device__ __forceinline__ void ldmatrix_x2(uint32_t* r, uint32_t addr) {
    asm volatile("ldmatrix.sync.aligned.m8n8.x2.shared.b16 {%0,%1}, [%2];"
                 : "=r"(r[0]), "=r"(r[1]) : "r"(addr));
}
__device__ __forceinline__ void mma16816h(float* d, const uint32_t* a, const uint32_t* b) {
    asm volatile("mma.sync.aligned.m16n8k16.row.col.f32.f16.f16.f32 "
                 "{%0,%1,%2,%3}, {%4,%5,%6,%7}, {%8,%9}, {%0,%1,%2,%3};"
                 : "+f"(d[0]), "+f"(d[1]), "+f"(d[2]), "+f"(d[3])
                 : "r"(a[0]), "r"(a[1]), "r"(a[2]), "r"(a[3]), "r"(b[0]), "r"(b[1]));
}
__device__ __forceinline__ float4 h4_to_f4(uint2 u) {
    __half2 a = *reinterpret_cast<__half2*>(&u.x);
    __half2 b = *reinterpret_cast<__half2*>(&u.y);
    float2 fa = __half22float2(a), fb = __half22float2(b);
    return make_float4(fa.x, fa.y, fb.x, fb.y);
}
__device__ __forceinline__ uint2 f4_to_h4(float4 f) {
    __half2 a = __floats2half2_rn(f.x, f.y);
    __half2 b = __floats2half2_rn(f.z, f.w);
    uint2 u;
    u.x = *reinterpret_cast<uint32_t*>(&a);
    u.y = *reinterpret_cast<uint32_t*>(&b);
    return u;
}

// ---------------- setup kernels ------------------------------------------------
__global__ void k_init() {
    int i = blockIdx.x*blockDim.x + threadIdx.x;
    if (i < NP) d_nperm[i] = -1;
    if (i < NN) d_deg[i] = 0;
    if (i < TT) d_tcnt[i] = 0;
}
__global__ void k_count(const int* __restrict__ ntypes, const int* __restrict__ dst) {
    __shared__ int sh[TT];
    if (threadIdx.x < TT) sh[threadIdx.x] = 0;
    __syncthreads();
    int i = blockIdx.x*blockDim.x + threadIdx.x;
    if (i < NN) atomicAdd(&sh[ntypes[i]], 1);
    if (i < EE) atomicAdd(&d_deg[dst[i]], 1);
    __syncthreads();
    if (threadIdx.x < TT && sh[threadIdx.x]) atomicAdd(&d_tcnt[threadIdx.x], sh[threadIdx.x]);
}
__global__ void k_toffsets() {
    int run = 0;
    for (int t = 0; t < TT; t++) {
        d_topad[t] = run; d_tcur[t] = run;
        run += ((d_tcnt[t] + 127) / 128) * 128;
    }
    d_topad[TT] = run;
}
__global__ void k_scatter_nodes(const int* __restrict__ ntypes) {
    __shared__ int scnt[TT], sbase[TT];
    if (threadIdx.x < TT) scnt[threadIdx.x] = 0;
    __syncthreads();
    int i = blockIdx.x*blockDim.x + threadIdx.x;
    int t = 0, myidx = 0;
    bool valid = (i < NN);
    if (valid) { t = ntypes[i]; myidx = atomicAdd(&scnt[t], 1); }
    __syncthreads();
    if (threadIdx.x < TT) sbase[threadIdx.x] = atomicAdd(&d_tcur[threadIdx.x], scnt[threadIdx.x]);
    __syncthreads();
    if (valid) {
        int p = sbase[t] + myidx;
        d_nperm[p] = i;
        d_iperm[i] = p;
    }
}
__device__ __forceinline__ int block_scan_incl(int x, int* wsum) {
    unsigned full = 0xffffffffu;
    int lane = threadIdx.x & 31, wid = threadIdx.x >> 5;
    int v = x;
    #pragma unroll
    for (int d = 1; d < 32; d <<= 1) {
        int t = __shfl_up_sync(full, v, d);
        if (lane >= d) v += t;
    }
    if (lane == 31) wsum[wid] = v;
    __syncthreads();
    if (threadIdx.x == 0) {
        int run = 0;
        #pragma unroll
        for (int w = 0; w < 8; w++) { int t = wsum[w]; wsum[w] = run; run += t; }
    }
    __syncthreads();
    return v + wsum[wid];
}
__global__ void k_scan1() {
    __shared__ int wsum[8];
    int i = blockIdx.x*256 + threadIdx.x;
    int x = (i < NN) ? d_deg[i] : 0;
    int inc = block_scan_incl(x, wsum);
    if (i < NN) d_off[i] = inc - x;
    if (threadIdx.x == 255) d_bsum[blockIdx.x] = inc;
}
__global__ void k_scan2(int nblocks) {
    __shared__ int wsum[8];
    int t = threadIdx.x;
    int x = (t < nblocks) ? d_bsum[t] : 0;
    int inc = block_scan_incl(x, wsum);
    d_bpre[t] = inc - x;
}
__global__ void k_scan3() {
    int i = blockIdx.x*256 + threadIdx.x;
    if (i < NN) {
        int v = d_off[i] + d_bpre[i >> 8];
        d_off[i] = v; d_cursor[i] = v;
    }
    if (i == 0) d_off[NN] = EE;
}
__global__ void k_scatter_edges(const int* __restrict__ src, const int* __restrict__ dst,
                                const int* __restrict__ et) {
    int e = blockIdx.x*blockDim.x + threadIdx.x;
    if (e < EE) {
        int pos = atomicAdd(&d_cursor[dst[e]], 1);
        d_epack[pos] = (d_iperm[src[e]] << 2) | et[e];
    }
}

// ---------------- weight pack: plain + composite chunks -------------------------
// chunk map: 0..5 adapt (t=c>>1, khalf=c&1)
// per layer l at base 6+l*30: s=0..2 q(t=s); s=3..26 composite
//   (sc=s-3: isV=sc/12, r=(sc%12)/3, t=sc%3); s=27..29 att(t=s-27)
__global__ void k_wprep(const float* __restrict__ Wad,
                        const float* __restrict__ Wk, const float* __restrict__ bk,
                        const float* __restrict__ Wq,
                        const float* __restrict__ Wv, const float* __restrict__ bv,
                        const float* __restrict__ Wa,
                        const float* __restrict__ Ratt, const float* __restrict__ Rmsg,
                        const float* __restrict__ pri) {
    int c = blockIdx.x;
    int tid = threadIdx.x;
    __half* oh = d_wpack + (size_t)c * 16384;

    if (c < 6) {
        int t = c >> 1, k0 = (c & 1) * 128;
        const float* W = Wad + (size_t)t * 256 * 128;
        for (int i = tid; i < 16384; i += 256) {
            int n = i >> 7, k = i & 127;
            oh[n*128 + k] = __float2half_rn(W[(size_t)(k0 + k) * 128 + n]);
        }
        return;
    }
    int cc = c - 6, l = cc / 30, s = cc % 30;
    if (s < 3 || s >= 27) {
        const float* W = (s < 3) ? (Wq + (size_t)(l*3 + s) * 16384)
                                 : (Wa + (size_t)(l*3 + (s-27)) * 16384);
        for (int i = tid; i < 16384; i += 256) {
            int n = i >> 7, k = i & 127;
            oh[n*128 + k] = __float2half_rn(W[(size_t)k * 128 + n]);
        }
        return;
    }
    // composite
    int sc = s - 3;
    int isV = sc / 12, rem = sc % 12, r = rem / 3, t = rem % 3;
    const float* Ws = (isV ? Wv : Wk) + (size_t)(l*3 + t) * 16384;
    const float* Rm = (isV ? Rmsg : Ratt) + (size_t)(l*RR + r) * HH * 256;  // [h][d][f]
    const float* bs = (isV ? bv : bk) + (l*3 + t) * 128;
    for (int i = tid; i < 16384; i += 256) {
        int n = i >> 7, k = i & 127;
        int h = n >> 4, f = n & 15;
        const float* wrow = Ws + (size_t)k * 128 + h * 16;
        const float* rcol = Rm + h * 256 + f;
        float acc = 0.f;
        #pragma unroll
        for (int d = 0; d < 16; d++) acc = fmaf(wrow[d], rcol[d*16], acc);
        float ps = isV ? 1.0f : (__ldg(&pri[l*RR*HH + r*HH + h]) * 0.25f);
        oh[n*128 + k] = __float2half_rn(acc * ps);
    }
    if (tid < 128) {
        int n = tid, h = n >> 4, f = n & 15;
        const float* rcol = Rm + h * 256 + f;
        float acc = 0.f;
        #pragma unroll
        for (int d = 0; d < 16; d++) acc = fmaf(bs[h*16 + d], rcol[d*16], acc);
        float ps = isV ? 1.0f : (__ldg(&pri[l*RR*HH + r*HH + h]) * 0.25f);
        d_bcomp[c*128 + n] = acc * ps;
    }
}

// ---------------- HMMA GEMM core (fp16 single-term A) ---------------------------
#define SROW   136
#define OFF_A  0
#define OFF_B  34816
#define GSMEM  69632

// GATHER: 0 contiguous, 1 gather via nperm, 2 contiguous + GELU
// EPI: 1 tanh->f32(outf), 2 f16(outh), 3 combine1(LN+ReLU->d_h1),
//      4 combine2(->outfinal via nperm), 5 f16 kvrel at kvoff
template<int GATHER, int EPI>
__device__ __forceinline__ void gemm_core(const float* __restrict__ A, int nch, int cbase,
                                          const float* __restrict__ bias,
                                          float* __restrict__ outf, __half* __restrict__ outh,
                                          const float* __restrict__ hx,
                                          const float* __restrict__ skip,
                                          const float* __restrict__ gamma,
                                          const float* __restrict__ beta,
                                          float* __restrict__ outfinal,
                                          int kvoff) {
    extern __shared__ char smem[];
    const uint32_t sb = smem_u32(smem);
    const int tid = threadIdx.x;
    const int wid = tid >> 5, lane = tid & 31;
    const int base = blockIdx.x * 128;
    const int t = (base >= d_topad[1]) + (base >= d_topad[2]);
    const float* bt = bias + t * 128;
    const int lda = nch * 128;
    const int wm = wid & 3, wn = wid >> 2;

    float acc[2][8][4];
    #pragma unroll
    for (int mi = 0; mi < 2; mi++)
        #pragma unroll
        for (int nj = 0; nj < 8; nj++)
            #pragma unroll
            for (int e = 0; e < 4; e++) acc[mi][nj][e] = 0.f;

    const uint32_t aoff = (uint32_t)((wm*32 + (lane & 15)) * SROW + (lane >> 4) * 8) * 2;
    const int l16 = lane & 15;
    const uint32_t boff = (uint32_t)((wn*64 + (l16 & 7)) * SROW + (l16 >> 3) * 8) * 2;

    for (int kc = 0; kc < nch; kc++) {
        if (kc > 0) __syncthreads();
        {
            int chunk = cbase + t * nch + kc;
            const uint4* bsrc = (const uint4*)(d_wpack + (size_t)chunk * 16384);
            #pragma unroll
            for (int i = 0; i < 8; i++) {
                int idx = tid + i * 256;
                int n = idx >> 4, k8g = idx & 15;
                uint32_t doff = (uint32_t)(n * SROW + k8g * 8) * 2;
                *(uint4*)(smem + OFF_B + doff) = bsrc[idx];
            }
        }
        #pragma unroll
        for (int i = 0; i < 8; i++) {
            int gi = tid + i * 256;
            int row = gi >> 4;
            int k8 = (gi & 15) * 8;
            float v[8];
            if (GATHER == 1) {
                int rn = d_nperm[base + row];
                if (rn >= 0) {
                    const float4* ap = (const float4*)(A + (size_t)rn * lda + kc*128 + k8);
                    float4 a0 = ap[0], a1 = ap[1];
                    v[0]=a0.x; v[1]=a0.y; v[2]=a0.z; v[3]=a0.w;
                    v[4]=a1.x; v[5]=a1.y; v[6]=a1.z; v[7]=a1.w;
                } else {
                    #pragma unroll
                    for (int j = 0; j < 8; j++) v[j] = 0.f;
                }
            } else {
                const float4* ap = (const float4*)(A + (size_t)(base + row) * lda + kc*128 + k8);
                float4 a0 = ap[0], a1 = ap[1];
                v[0]=a0.x; v[1]=a0.y; v[2]=a0.z; v[3]=a0.w;
                v[4]=a1.x; v[5]=a1.y; v[6]=a1.z; v[7]=a1.w;
                if (GATHER == 2) {
                    #pragma unroll
                    for (int j = 0; j < 8; j++)
                        v[j] = 0.5f * v[j] * (1.0f + erff(v[j] * 0.70710678118654752f));
                }
            }
            union { __half b[8]; uint4 u; } ph;
            #pragma unroll
            for (int j = 0; j < 8; j++) ph.b[j] = __float2half_rn(v[j]);
            *(uint4*)(smem + OFF_A + (uint32_t)(row * SROW + k8) * 2) = ph.u;
        }
        __syncthreads();

        #pragma unroll
        for (int ks = 0; ks < 8; ks++) {
            uint32_t ah[2][4];
            #pragma unroll
            for (int mi = 0; mi < 2; mi++) {
                uint32_t ad = sb + aoff + (uint32_t)(mi*16*SROW + ks*16) * 2;
                ldmatrix_x4(ah[mi], ad + OFF_A);
            }
            uint32_t bf[8][2];
            #pragma unroll
            for (int nj = 0; nj < 8; nj++) {
                uint32_t bd = sb + boff + (uint32_t)(nj*8*SROW + ks*16) * 2;
                ldmatrix_x2(bf[nj], bd + OFF_B);
            }
            #pragma unroll
            for (int mi = 0; mi < 2; mi++)
                #pragma unroll
                for (int nj = 0; nj < 8; nj++)
                    mma16816h(acc[mi][nj], ah[mi], bf[nj]);
        }
    }
    __syncthreads();

    float* stage = (float*)smem;              // [128][132]
    #pragma unroll
    for (int mi = 0; mi < 2; mi++) {
        #pragma unroll
        for (int nj = 0; nj < 8; nj++) {
            int row = wm*32 + mi*16 + (lane >> 2);
            int col = wn*64 + nj*8 + 2*(lane & 3);
            float b0 = __ldg(&bt[col]), b1 = __ldg(&bt[col+1]);
            float v0 = acc[mi][nj][0] + b0;
            float v1 = acc[mi][nj][1] + b1;
            float v2 = acc[mi][nj][2] + b0;
            float v3 = acc[mi][nj][3] + b1;
            if (EPI == 1) { v0 = tanhf(v0); v1 = tanhf(v1); v2 = tanhf(v2); v3 = tanhf(v3); }
            stage[row*132 + col]     = v0;
            stage[row*132 + col + 1] = v1;
            stage[(row+8)*132 + col]     = v2;
            stage[(row+8)*132 + col + 1] = v3;
        }
    }
    __syncthreads();

    if (EPI == 1) {
        for (int i = tid; i < 4096; i += 256) {
            int row = i >> 5, c4 = i & 31;
            *(float4*)(outf + ((size_t)(base + row)) * 128 + c4 * 4) =
                *(const float4*)(stage + row * 132 + c4 * 4);
        }
    } else if (EPI == 2) {
        for (int i = tid; i < 4096; i += 256) {
            int row = i >> 5, c4 = i & 31;
            float4 f = *(const float4*)(stage + row * 132 + c4 * 4);
            *(uint2*)(outh + (size_t)(base + row) * 128 + c4 * 4) = f4_to_h4(f);
        }
    } else if (EPI == 5) {
        for (int i = tid; i < 4096; i += 256) {
            int row = i >> 5, c4 = i & 31;
            float4 f = *(const float4*)(stage + row * 132 + c4 * 4);
            *(uint2*)(d_kvrel + (size_t)(base + row) * 1024 + kvoff + c4 * 4) = f4_to_h4(f);
        }
    } else if (EPI == 3 || EPI == 4) {
        const unsigned full = 0xffffffffu;
        float alpha = 1.0f / (1.0f + __expf(-__ldg(&skip[t])));
        float ia = 1.0f - alpha;
        float4 g4, b4;
        if (EPI == 3) {
            g4 = *(const float4*)(gamma + t*128 + lane*4);
            b4 = *(const float4*)(beta  + t*128 + lane*4);
        }
        #pragma unroll
        for (int i = 0; i < 16; i++) {
            int row = wid*16 + i;
            float4 tr = *(const float4*)(stage + row*132 + lane*4);
            float4 hx4 = *(const float4*)(hx + (size_t)(base+row)*128 + lane*4);
            float4 o;
            o.x = tr.x*alpha + hx4.x*ia;
            o.y = tr.y*alpha + hx4.y*ia;
            o.z = tr.z*alpha + hx4.z*ia;
            o.w = tr.w*alpha + hx4.w*ia;
            if (EPI == 3) {
                float sm = o.x + o.y + o.z + o.w;
                float sq = o.x*o.x + o.y*o.y + o.z*o.z + o.w*o.w;
                #pragma unroll
                for (int d = 16; d; d >>= 1) {
                    sm += __shfl_xor_sync(full, sm, d);
                    sq += __shfl_xor_sync(full, sq, d);
                }
                float mean = sm * (1.0f/128.0f);
                float var  = sq * (1.0f/128.0f) - mean*mean;
                float rstd = rsqrtf(var + 1e-5f);
                float4 y;
                y.x = fmaxf((o.x-mean)*rstd*g4.x + b4.x, 0.f);
                y.y = fmaxf((o.y-mean)*rstd*g4.y + b4.y, 0.f);
                y.z = fmaxf((o.z-mean)*rstd*g4.z + b4.z, 0.f);
                y.w = fmaxf((o.w-mean)*rstd*g4.w + b4.w, 0.f);
                *(float4*)(d_h1 + (size_t)(base+row)*128 + lane*4) = y;
            } else {
                int node = d_nperm[base + row];
                if (node >= 0)
                    *(float4*)(outfinal + (size_t)node*128 + lane*4) = o;
            }
        }
    }
}

__global__ void __launch_bounds__(256,2)
k_gemm_adapt(const float* __restrict__ x, const float* __restrict__ bad) {
    gemm_core<1,1>(x, 2, 0, bad, d_h0, nullptr, nullptr, nullptr, nullptr, nullptr, nullptr, 0);
}
// grid (NTILE, 9): y=0 q; y=1..8: kvrel slots
__global__ void __launch_bounds__(256,2)
k_gemm_qkv9(int l, const float* __restrict__ bq) {
    const float* A = l ? d_h1 : d_h0;
    int lbase = 6 + l*30;
    int s = blockIdx.y;
    if (s == 0) {
        gemm_core<0,2>(A, 1, lbase, bq + l*TT*HIDD, nullptr, d_qh,
                       nullptr, nullptr, nullptr, nullptr, nullptr, 0);
    } else {
        int isV = (s-1) >> 2, r = (s-1) & 3;
        int cbase = lbase + 3 + isV*12 + r*3;
        int kvoff = r*256 + isV*128;
        gemm_core<0,5>(A, 1, cbase, d_bcomp + cbase*128, nullptr, nullptr,
                       nullptr, nullptr, nullptr, nullptr, nullptr, kvoff);
    }
}
__global__ void __launch_bounds__(256,2)
k_gemm_att0(int cb, const float* __restrict__ ba, const float* __restrict__ skip,
            const float* __restrict__ gamma, const float* __restrict__ beta) {
    gemm_core<2,3>(d_agg, 1, cb, ba, nullptr, nullptr, d_h0, skip, gamma, beta, nullptr, 0);
}
__global__ void __launch_bounds__(256,2)
k_gemm_att1(int cb, const float* __restrict__ ba, const float* __restrict__ skip,
            float* __restrict__ out) {
    gemm_core<2,4>(d_agg, 1, cb, ba, nullptr, nullptr, d_h1, skip, nullptr, nullptr, out, 0);
}

// ---------------- edge phase: warp-per-dst, online softmax ---------------------
__device__ __forceinline__ void edge_step(uint2 kr, uint2 vr, const float4 q4,
                                          float& m, float& s, float4& acc) {
    const unsigned full = 0xffffffffu;
    float4 k4 = h4_to_f4(kr);
    float4 v4 = h4_to_f4(vr);
    float p = q4.x*k4.x + q4.y*k4.y + q4.z*k4.z + q4.w*k4.w;
    p += __shfl_xor_sync(full, p, 1);
    p += __shfl_xor_sync(full, p, 2);
    float mn = fmaxf(m, p);
    float corr = __expf(m - mn);
    float w = __expf(p - mn);
    s = s*corr + w;
    acc.x = fmaf(w, v4.x, acc.x*corr);
    acc.y = fmaf(w, v4.y, acc.y*corr);
    acc.z = fmaf(w, v4.z, acc.z*corr);
    acc.w = fmaf(w, v4.w, acc.w*corr);
    m = mn;
}

__global__ void k_edge() {
    const int n = (blockIdx.x*blockDim.x + threadIdx.x) >> 5;
    if (n >= NN) return;
    const int lane = threadIdx.x & 31;

    const int ip = d_iperm[n];
    float4 q4 = h4_to_f4(*(const uint2*)(d_qh + (size_t)ip*128 + lane*4));
    const int beg = d_off[n], end = d_off[n+1];

    float m = -1e30f, s = 0.f;
    float4 acc = make_float4(0.f,0.f,0.f,0.f);

    int e = beg;
    for (; e + 1 < end; e += 2) {
        int pk0 = d_epack[e], pk1 = d_epack[e+1];
        const __half* b0 = d_kvrel + (size_t)pk0*256;
        const __half* b1 = d_kvrel + (size_t)pk1*256;
        uint2 k0 = *(const uint2*)(b0 + lane*4);
        uint2 v0 = *(const uint2*)(b0 + 128 + lane*4);
        uint2 k1 = *(const uint2*)(b1 + lane*4);
        uint2 v1 = *(const uint2*)(b1 + 128 + lane*4);
        edge_step(k0, v0, q4, m, s, acc);
        edge_step(k1, v1, q4, m, s, acc);
    }
    if (e < end) {
        int pk0 = d_epack[e];
        const __half* b0 = d_kvrel + (size_t)pk0*256;
        uint2 k0 = *(const uint2*)(b0 + lane*4);
        uint2 v0 = *(const uint2*)(b0 + 128 + lane*4);
        edge_step(k0, v0, q4, m, s, acc);
    }
    float inv = 1.0f / fmaxf(s, 1e-9f);
    acc.x *= inv; acc.y *= inv; acc.z *= inv; acc.w *= inv;
    ((float4*)d_agg)[(size_t)ip*32 + lane] = acc;
}

// ---------------- launch --------------------------------------------------------
extern "C" void kernel_launch(void* const* d_in, const int* in_sizes, int n_in,
                              void* d_out, int out_size) {
    const float* x      = (const float*)d_in[0];
    const int*   ntypes = (const int*)d_in[1];
    const int*   ei     = (const int*)d_in[2];
    const int*   et     = (const int*)d_in[3];
    const float* Wad    = (const float*)d_in[4];
    const float* bad    = (const float*)d_in[5];
    const float* Wk     = (const float*)d_in[6];
    const float* bk     = (const float*)d_in[7];
    const float* Wq     = (const float*)d_in[8];
    const float* bq     = (const float*)d_in[9];
    const float* Wv     = (const float*)d_in[10];
    const float* bv     = (const float*)d_in[11];
    const float* Wa     = (const float*)d_in[12];
    const float* ba     = (const float*)d_in[13];
    const float* pri    = (const float*)d_in[14];
    const float* ratt   = (const float*)d_in[15];
    const float* rmsg   = (const float*)d_in[16];
    const float* skip   = (const float*)d_in[17];
    const float* gamma  = (const float*)d_in[18];
    const float* beta   = (const float*)d_in[19];
    float* out = (float*)d_out;

    const int* srcA = ei;
    const int* dstA = ei + EE;

    cudaFuncSetAttribute(k_gemm_adapt, cudaFuncAttributeMaxDynamicSharedMemorySize, GSMEM);
    cudaFuncSetAttribute(k_gemm_qkv9,  cudaFuncAttributeMaxDynamicSharedMemorySize, GSMEM);
    cudaFuncSetAttribute(k_gemm_att0,  cudaFuncAttributeMaxDynamicSharedMemorySize, GSMEM);
    cudaFuncSetAttribute(k_gemm_att1,  cudaFuncAttributeMaxDynamicSharedMemorySize, GSMEM);

    const int SCAN_BLK = (NN + 255) / 256;
    const int WARP_BLK = (NN*32 + 255) / 256;

    k_init<<<(NP+255)/256, 256>>>();
    k_count<<<(EE+255)/256, 256>>>(ntypes, dstA);
    k_toffsets<<<1, 1>>>();
    k_scatter_nodes<<<(NN+255)/256, 256>>>(ntypes);
    k_scan1<<<SCAN_BLK, 256>>>();
    k_scan2<<<1, 256>>>(SCAN_BLK);
    k_scan3<<<SCAN_BLK, 256>>>();
    k_scatter_edges<<<(EE+255)/256, 256>>>(srcA, dstA, et);
    k_wprep<<<NCHUNKS, 256>>>(Wad, Wk, bk, Wq, Wv, bv, Wa, ratt, rmsg, pri);

    k_gemm_adapt<<<NTILE, 256, GSMEM>>>(x, bad);

    for (int l = 0; l < 2; l++) {
        int lbase = 6 + l*30;
        k_gemm_qkv9<<<dim3(NTILE,9), 256, GSMEM>>>(l, bq);
        k_edge<<<WARP_BLK, 256>>>();
        if (l == 0) {
            k_gemm_att0<<<NTILE, 256, GSMEM>>>(lbase + 27, ba + l*TT*HIDD, skip + l*TT, gamma, beta);
        } else {
            k_gemm_att1<<<NTILE, 256, GSMEM>>>(lbase + 27, ba + l*TT*HIDD, skip + l*TT, out);
        }
    }
}

// round 8
// speedup vs baseline: 1.0257x; 1.0257x over previous
#include <cuda_runtime.h>
#include <cuda_fp16.h>
#include <cstdint>
#include <math.h>

#define NN   50000
#define EE   400000
#define IND  256
#define HIDD 128
#define TT   3
#define RR   4
#define HH   8
#define DKK  16
#define NP   50432          // 394 blocks * 128
#define NTILE 394
#define NCHUNKS 66          // 6 adapt + 2*(3 q + 24 composite + 3 att)

// ---------------- scratch (static device globals) -----------------------------
__device__ float d_h0[NP*HIDD];
__device__ float d_h1[NP*HIDD];
__device__ __half d_aggh[NP*HIDD];
__device__ __half d_qh[NP*HIDD];
__device__ __half d_kvrel[(size_t)NP*RR*256];   // [p*4+r][0:128]=krel*pri/4, [128:256]=vrel
__device__ __half d_wpack[NCHUNKS*16384];
__device__ float  d_bcomp[NCHUNKS*128];
__device__ int   d_deg[NN];
__device__ int   d_off[NN+1];
__device__ int   d_cursor[NN];
__device__ int   d_epack[EE];
__device__ int   d_bsum[256];
__device__ int   d_bpre[256];
__device__ int   d_tcnt[TT];
__device__ int   d_topad[TT+1];
__device__ int   d_tcur[TT];
__device__ int   d_nperm[NP];
__device__ int   d_iperm[NN];

// ---------------- helpers -------------------------------------------------------
__device__ __forceinline__ uint32_t smem_u32(const void* p) {
    uint32_t a;
    asm("{ .reg .u64 t; cvta.to.shared.u64 t, %1; cvt.u32.u64 %0, t; }" : "=r"(a) : "l"(p));
    return a;
}
__device__ __forceinline__ void ldmatrix_x4(uint32_t* r, uint32_t addr) {
    asm volatile("ldmatrix.sync.aligned.m8n8.x4.shared.b16 {%0,%1,%2,%3}, [%4];"
                 : "=r"(r[0]), "=r"(r[1]), "=r"(r[2]), "=r"(r[3]) : "r"(addr));
}
__device__ __forceinline__ void ldmatrix_x2(uint32_t* r, uint32_t addr) {
    asm volatile("ldmatrix.sync.aligned.m8n8.x2.shared.b16 {%0,%1}, [%2];"
                 : "=r"(r[0]), "=r"(r[1]) : "r"(addr));
}
__device__ __forceinline__ void mma16816h(float* d, const uint32_t* a, const uint32_t* b) {
    asm volatile("mma.sync.aligned.m16n8k16.row.col.f32.f16.f16.f32 "
                 "{%0,%1,%2,%3}, {%4,%5,%6,%7}, {%8,%9}, {%0,%1,%2,%3};"
                 : "+f"(d[0]), "+f"(d[1]), "+f"(d[2]), "+f"(d[3])
                 : "r"(a[0]), "r"(a[1]), "r"(a[2]), "r"(a[3]), "r"(b[0]), "r"(b[1]));
}
__device__ __forceinline__ float4 h4_to_f4(uint2 u) {
    __half2 a = *reinterpret_cast<__half2*>(&u.x);
    __half2 b = *reinterpret_cast<__half2*>(&u.y);
    float2 fa = __half22float2(a), fb = __half22float2(b);
    return make_float4(fa.x, fa.y, fb.x, fb.y);
}
__device__ __forceinline__ uint2 f4_to_h4(float4 f) {
    __half2 a = __floats2half2_rn(f.x, f.y);
    __half2 b = __floats2half2_rn(f.z, f.w);
    uint2 u;
    u.x = *reinterpret_cast<uint32_t*>(&a);
    u.y = *reinterpret_cast<uint32_t*>(&b);
    return u;
}

// ---------------- setup kernels ------------------------------------------------
__global__ void k_init() {
    int i = blockIdx.x*blockDim.x + threadIdx.x;
    if (i < NP) d_nperm[i] = -1;
    if (i < NN) d_deg[i] = 0;
    if (i < TT) d_tcnt[i] = 0;
}
__global__ void k_count(const int* __restrict__ ntypes, const int* __restrict__ dst) {
    __shared__ int sh[TT];
    if (threadIdx.x < TT) sh[threadIdx.x] = 0;
    __syncthreads();
    int i = blockIdx.x*blockDim.x + threadIdx.x;
    if (i < NN) atomicAdd(&sh[ntypes[i]], 1);
    if (i < EE) atomicAdd(&d_deg[dst[i]], 1);
    __syncthreads();
    if (threadIdx.x < TT && sh[threadIdx.x]) atomicAdd(&d_tcnt[threadIdx.x], sh[threadIdx.x]);
}
__global__ void k_toffsets() {
    int run = 0;
    for (int t = 0; t < TT; t++) {
        d_topad[t] = run; d_tcur[t] = run;
        run += ((d_tcnt[t] + 127) / 128) * 128;
    }
    d_topad[TT] = run;
}
__global__ void k_scatter_nodes(const int* __restrict__ ntypes) {
    __shared__ int scnt[TT], sbase[TT];
    if (threadIdx.x < TT) scnt[threadIdx.x] = 0;
    __syncthreads();
    int i = blockIdx.x*blockDim.x + threadIdx.x;
    int t = 0, myidx = 0;
    bool valid = (i < NN);
    if (valid) { t = ntypes[i]; myidx = atomicAdd(&scnt[t], 1); }
    __syncthreads();
    if (threadIdx.x < TT) sbase[threadIdx.x] = atomicAdd(&d_tcur[threadIdx.x], scnt[threadIdx.x]);
    __syncthreads();
    if (valid) {
        int p = sbase[t] + myidx;
        d_nperm[p] = i;
        d_iperm[i] = p;
    }
}
__device__ __forceinline__ int block_scan_incl(int x, int* wsum) {
    unsigned full = 0xffffffffu;
    int lane = threadIdx.x & 31, wid = threadIdx.x >> 5;
    int v = x;
    #pragma unroll
    for (int d = 1; d < 32; d <<= 1) {
        int t = __shfl_up_sync(full, v, d);
        if (lane >= d) v += t;
    }
    if (lane == 31) wsum[wid] = v;
    __syncthreads();
    if (threadIdx.x == 0) {
        int run = 0;
        #pragma unroll
        for (int w = 0; w < 8; w++) { int t = wsum[w]; wsum[w] = run; run += t; }
    }
    __syncthreads();
    return v + wsum[wid];
}
__global__ void k_scan1() {
    __shared__ int wsum[8];
    int i = blockIdx.x*256 + threadIdx.x;
    int x = (i < NN) ? d_deg[i] : 0;
    int inc = block_scan_incl(x, wsum);
    if (i < NN) d_off[i] = inc - x;
    if (threadIdx.x == 255) d_bsum[blockIdx.x] = inc;
}
__global__ void k_scan2(int nblocks) {
    __shared__ int wsum[8];
    int t = threadIdx.x;
    int x = (t < nblocks) ? d_bsum[t] : 0;
    int inc = block_scan_incl(x, wsum);
    d_bpre[t] = inc - x;
}
__global__ void k_scan3() {
    int i = blockIdx.x*256 + threadIdx.x;
    if (i < NN) {
        int v = d_off[i] + d_bpre[i >> 8];
        d_off[i] = v; d_cursor[i] = v;
    }
    if (i == 0) d_off[NN] = EE;
}
__global__ void k_scatter_edges(const int* __restrict__ src, const int* __restrict__ dst,
                                const int* __restrict__ et) {
    int e = blockIdx.x*blockDim.x + threadIdx.x;
    if (e < EE) {
        int pos = atomicAdd(&d_cursor[dst[e]], 1);
        d_epack[pos] = (d_iperm[src[e]] << 2) | et[e];
    }
}

// ---------------- weight pack: plain + composite chunks -------------------------
// chunk map: 0..5 adapt (t=c>>1, khalf=c&1)
// per layer l at base 6+l*30: s=0..2 q(t=s); s=3..26 composite
//   (sc=s-3: isV=sc/12, r=(sc%12)/3, t=sc%3); s=27..29 att(t=s-27)
__global__ void k_wprep(const float* __restrict__ Wad,
                        const float* __restrict__ Wk, const float* __restrict__ bk,
                        const float* __restrict__ Wq,
                        const float* __restrict__ Wv, const float* __restrict__ bv,
                        const float* __restrict__ Wa,
                        const float* __restrict__ Ratt, const float* __restrict__ Rmsg,
                        const float* __restrict__ pri) {
    int c = blockIdx.x;
    int tid = threadIdx.x;
    __half* oh = d_wpack + (size_t)c * 16384;

    if (c < 6) {
        int t = c >> 1, k0 = (c & 1) * 128;
        const float* W = Wad + (size_t)t * 256 * 128;
        for (int i = tid; i < 16384; i += 256) {
            int n = i >> 7, k = i & 127;
            oh[n*128 + k] = __float2half_rn(W[(size_t)(k0 + k) * 128 + n]);
        }
        return;
    }
    int cc = c - 6, l = cc / 30, s = cc % 30;
    if (s < 3 || s >= 27) {
        const float* W = (s < 3) ? (Wq + (size_t)(l*3 + s) * 16384)
                                 : (Wa + (size_t)(l*3 + (s-27)) * 16384);
        for (int i = tid; i < 16384; i += 256) {
            int n = i >> 7, k = i & 127;
            oh[n*128 + k] = __float2half_rn(W[(size_t)k * 128 + n]);
        }
        return;
    }
    // composite
    int sc = s - 3;
    int isV = sc / 12, rem = sc % 12, r = rem / 3, t = rem % 3;
    const float* Ws = (isV ? Wv : Wk) + (size_t)(l*3 + t) * 16384;
    const float* Rm = (isV ? Rmsg : Ratt) + (size_t)(l*RR + r) * HH * 256;  // [h][d][f]
    const float* bs = (isV ? bv : bk) + (l*3 + t) * 128;
    for (int i = tid; i < 16384; i += 256) {
        int n = i >> 7, k = i & 127;
        int h = n >> 4, f = n & 15;
        const float* wrow = Ws + (size_t)k * 128 + h * 16;
        const float* rcol = Rm + h * 256 + f;
        float acc = 0.f;
        #pragma unroll
        for (int d = 0; d < 16; d++) acc = fmaf(wrow[d], rcol[d*16], acc);
        float ps = isV ? 1.0f : (__ldg(&pri[l*RR*HH + r*HH + h]) * 0.25f);
        oh[n*128 + k] = __float2half_rn(acc * ps);
    }
    if (tid < 128) {
        int n = tid, h = n >> 4, f = n & 15;
        const float* rcol = Rm + h * 256 + f;
        float acc = 0.f;
        #pragma unroll
        for (int d = 0; d < 16; d++) acc = fmaf(bs[h*16 + d], rcol[d*16], acc);
        float ps = isV ? 1.0f : (__ldg(&pri[l*RR*HH + r*HH + h]) * 0.25f);
        d_bcomp[c*128 + n] = acc * ps;
    }
}

// ---------------- smem layout ----------------------------------------------------
#define SROW   136
#define OFF_A  0
#define OFF_B  34816
#define GSMEM  69632

// ---------------- generic GEMM core (adapt / att) --------------------------------
// GATHER: 1 gather fp32 rows via nperm, 3 contiguous fp16 + GELU
// EPI: 1 tanh->f32(outf), 3 combine1(LN+ReLU->d_h1), 4 combine2(->outfinal via nperm)
template<int GATHER, int EPI>
__device__ __forceinline__ void gemm_core(const void* __restrict__ Av, int nch, int cbase,
                                          const float* __restrict__ bias,
                                          float* __restrict__ outf,
                                          const float* __restrict__ hx,
                                          const float* __restrict__ skip,
                                          const float* __restrict__ gamma,
                                          const float* __restrict__ beta,
                                          float* __restrict__ outfinal) {
    extern __shared__ char smem[];
    const uint32_t sb = smem_u32(smem);
    const int tid = threadIdx.x;
    const int wid = tid >> 5, lane = tid & 31;
    const int base = blockIdx.x * 128;
    const int t = (base >= d_topad[1]) + (base >= d_topad[2]);
    const float* bt = bias + t * 128;
    const int lda = nch * 128;
    const int wm = wid & 3, wn = wid >> 2;

    float acc[2][8][4];
    #pragma unroll
    for (int mi = 0; mi < 2; mi++)
        #pragma unroll
        for (int nj = 0; nj < 8; nj++)
            #pragma unroll
            for (int e = 0; e < 4; e++) acc[mi][nj][e] = 0.f;

    const uint32_t aoff = (uint32_t)((wm*32 + (lane & 15)) * SROW + (lane >> 4) * 8) * 2;
    const int l16 = lane & 15;
    const uint32_t boff = (uint32_t)((wn*64 + (l16 & 7)) * SROW + (l16 >> 3) * 8) * 2;

    for (int kc = 0; kc < nch; kc++) {
        if (kc > 0) __syncthreads();
        {
            int chunk = cbase + t * nch + kc;
            const uint4* bsrc = (const uint4*)(d_wpack + (size_t)chunk * 16384);
            #pragma unroll
            for (int i = 0; i < 8; i++) {
                int idx = tid + i * 256;
                int n = idx >> 4, k8g = idx & 15;
                uint32_t doff = (uint32_t)(n * SROW + k8g * 8) * 2;
                *(uint4*)(smem + OFF_B + doff) = bsrc[idx];
            }
        }
        #pragma unroll
        for (int i = 0; i < 8; i++) {
            int gi = tid + i * 256;
            int row = gi >> 4;
            int k8 = (gi & 15) * 8;
            if (GATHER == 1) {
                const float* A = (const float*)Av;
                float v[8];
                int rn = d_nperm[base + row];
                if (rn >= 0) {
                    const float4* ap = (const float4*)(A + (size_t)rn * lda + kc*128 + k8);
                    float4 a0 = ap[0], a1 = ap[1];
                    v[0]=a0.x; v[1]=a0.y; v[2]=a0.z; v[3]=a0.w;
                    v[4]=a1.x; v[5]=a1.y; v[6]=a1.z; v[7]=a1.w;
                } else {
                    #pragma unroll
                    for (int j = 0; j < 8; j++) v[j] = 0.f;
                }
                union { __half b[8]; uint4 u; } ph;
                #pragma unroll
                for (int j = 0; j < 8; j++) ph.b[j] = __float2half_rn(v[j]);
                *(uint4*)(smem + OFF_A + (uint32_t)(row * SROW + k8) * 2) = ph.u;
            } else {
                const __half* A = (const __half*)Av;
                uint4 raw = *(const uint4*)(A + (size_t)(base + row) * 128 + k8);
                union { __half b[8]; uint4 u; } ph;
                const __half2* hp = reinterpret_cast<const __half2*>(&raw);
                #pragma unroll
                for (int j = 0; j < 4; j++) {
                    float2 f2 = __half22float2(hp[j]);
                    f2.x = 0.5f * f2.x * (1.0f + erff(f2.x * 0.70710678118654752f));
                    f2.y = 0.5f * f2.y * (1.0f + erff(f2.y * 0.70710678118654752f));
                    ph.b[2*j]   = __float2half_rn(f2.x);
                    ph.b[2*j+1] = __float2half_rn(f2.y);
                }
                *(uint4*)(smem + OFF_A + (uint32_t)(row * SROW + k8) * 2) = ph.u;
            }
        }
        __syncthreads();

        #pragma unroll
        for (int ks = 0; ks < 8; ks++) {
            uint32_t ah[2][4];
            #pragma unroll
            for (int mi = 0; mi < 2; mi++) {
                uint32_t ad = sb + aoff + (uint32_t)(mi*16*SROW + ks*16) * 2;
                ldmatrix_x4(ah[mi], ad + OFF_A);
            }
            uint32_t bf[8][2];
            #pragma unroll
            for (int nj = 0; nj < 8; nj++) {
                uint32_t bd = sb + boff + (uint32_t)(nj*8*SROW + ks*16) * 2;
                ldmatrix_x2(bf[nj], bd + OFF_B);
            }
            #pragma unroll
            for (int mi = 0; mi < 2; mi++)
                #pragma unroll
                for (int nj = 0; nj < 8; nj++)
                    mma16816h(acc[mi][nj], ah[mi], bf[nj]);
        }
    }
    __syncthreads();

    float* stage = (float*)smem;              // [128][132]
    #pragma unroll
    for (int mi = 0; mi < 2; mi++) {
        #pragma unroll
        for (int nj = 0; nj < 8; nj++) {
            int row = wm*32 + mi*16 + (lane >> 2);
            int col = wn*64 + nj*8 + 2*(lane & 3);
            float b0 = __ldg(&bt[col]), b1 = __ldg(&bt[col+1]);
            float v0 = acc[mi][nj][0] + b0;
            float v1 = acc[mi][nj][1] + b1;
            float v2 = acc[mi][nj][2] + b0;
            float v3 = acc[mi][nj][3] + b1;
            if (EPI == 1) { v0 = tanhf(v0); v1 = tanhf(v1); v2 = tanhf(v2); v3 = tanhf(v3); }
            stage[row*132 + col]     = v0;
            stage[row*132 + col + 1] = v1;
            stage[(row+8)*132 + col]     = v2;
            stage[(row+8)*132 + col + 1] = v3;
        }
    }
    __syncthreads();

    if (EPI == 1) {
        for (int i = tid; i < 4096; i += 256) {
            int row = i >> 5, c4 = i & 31;
            *(float4*)(outf + ((size_t)(base + row)) * 128 + c4 * 4) =
                *(const float4*)(stage + row * 132 + c4 * 4);
        }
    } else {
        const unsigned full = 0xffffffffu;
        float alpha = 1.0f / (1.0f + __expf(-__ldg(&skip[t])));
        float ia = 1.0f - alpha;
        float4 g4, b4;
        if (EPI == 3) {
            g4 = *(const float4*)(gamma + t*128 + lane*4);
            b4 = *(const float4*)(beta  + t*128 + lane*4);
        }
        #pragma unroll
        for (int i = 0; i < 16; i++) {
            int row = wid*16 + i;
            float4 tr = *(const float4*)(stage + row*132 + lane*4);
            float4 hx4 = *(const float4*)(hx + (size_t)(base+row)*128 + lane*4);
            float4 o;
            o.x = tr.x*alpha + hx4.x*ia;
            o.y = tr.y*alpha + hx4.y*ia;
            o.z = tr.z*alpha + hx4.z*ia;
            o.w = tr.w*alpha + hx4.w*ia;
            if (EPI == 3) {
                float sm = o.x + o.y + o.z + o.w;
                float sq = o.x*o.x + o.y*o.y + o.z*o.z + o.w*o.w;
                #pragma unroll
                for (int d = 16; d; d >>= 1) {
                    sm += __shfl_xor_sync(full, sm, d);
                    sq += __shfl_xor_sync(full, sq, d);
                }
                float mean = sm * (1.0f/128.0f);
                float var  = sq * (1.0f/128.0f) - mean*mean;
                float rstd = rsqrtf(var + 1e-5f);
                float4 y;
                y.x = fmaxf((o.x-mean)*rstd*g4.x + b4.x, 0.f);
                y.y = fmaxf((o.y-mean)*rstd*g4.y + b4.y, 0.f);
                y.z = fmaxf((o.z-mean)*rstd*g4.z + b4.z, 0.f);
                y.w = fmaxf((o.w-mean)*rstd*g4.w + b4.w, 0.f);
                *(float4*)(d_h1 + (size_t)(base+row)*128 + lane*4) = y;
            } else {
                int node = d_nperm[base + row];
                if (node >= 0)
                    *(float4*)(outfinal + (size_t)node*128 + lane*4) = o;
            }
        }
    }
}

__global__ void __launch_bounds__(256,2)
k_gemm_adapt(const float* __restrict__ x, const float* __restrict__ bad) {
    gemm_core<1,1>(x, 2, 0, bad, d_h0, nullptr, nullptr, nullptr, nullptr, nullptr);
}
__global__ void __launch_bounds__(256,2)
k_gemm_att0(int cb, const float* __restrict__ ba, const float* __restrict__ skip,
            const float* __restrict__ gamma, const float* __restrict__ beta) {
    gemm_core<3,3>(d_aggh, 1, cb, ba, nullptr, d_h0, skip, gamma, beta, nullptr);
}
__global__ void __launch_bounds__(256,2)
k_gemm_att1(int cb, const float* __restrict__ ba, const float* __restrict__ skip,
            float* __restrict__ out) {
    gemm_core<3,4>(d_aggh, 1, cb, ba, nullptr, d_h1, skip, nullptr, nullptr, out);
}

// ---------------- fused q + 8x kvrel GEMM: A staged ONCE, loop over 9 B's --------
__global__ void __launch_bounds__(256,2)
k_gemm_qkv_all(int l, const float* __restrict__ bq) {
    extern __shared__ char smem[];
    const uint32_t sb = smem_u32(smem);
    const int tid = threadIdx.x;
    const int wid = tid >> 5, lane = tid & 31;
    const int base = blockIdx.x * 128;
    const int t = (base >= d_topad[1]) + (base >= d_topad[2]);
    const float* A = l ? d_h1 : d_h0;
    const int lbase = 6 + l*30;
    const int wm = wid & 3, wn = wid >> 2;

    // stage A (fp32 -> fp16) once
    #pragma unroll
    for (int i = 0; i < 8; i++) {
        int gi = tid + i * 256;
        int row = gi >> 4;
        int k8 = (gi & 15) * 8;
        const float4* ap = (const float4*)(A + (size_t)(base + row) * 128 + k8);
        float4 a0 = ap[0], a1 = ap[1];
        union { __half b[8]; uint4 u; } ph;
        ph.b[0]=__float2half_rn(a0.x); ph.b[1]=__float2half_rn(a0.y);
        ph.b[2]=__float2half_rn(a0.z); ph.b[3]=__float2half_rn(a0.w);
        ph.b[4]=__float2half_rn(a1.x); ph.b[5]=__float2half_rn(a1.y);
        ph.b[6]=__float2half_rn(a1.z); ph.b[7]=__float2half_rn(a1.w);
        *(uint4*)(smem + OFF_A + (uint32_t)(row * SROW + k8) * 2) = ph.u;
    }

    const uint32_t aoff = (uint32_t)((wm*32 + (lane & 15)) * SROW + (lane >> 4) * 8) * 2;
    const int l16 = lane & 15;
    const uint32_t boff = (uint32_t)((wn*64 + (l16 & 7)) * SROW + (l16 >> 3) * 8) * 2;

    for (int s = 0; s < 9; s++) {
        __syncthreads();   // A staged / previous B reads done
        int chunk = (s == 0) ? (lbase + t)
                             : (lbase + 3 + (((s-1) >> 2) * 12) + (((s-1) & 3) * 3) + t);
        {
            const uint4* bsrc = (const uint4*)(d_wpack + (size_t)chunk * 16384);
            #pragma unroll
            for (int i = 0; i < 8; i++) {
                int idx = tid + i * 256;
                int n = idx >> 4, k8g = idx & 15;
                *(uint4*)(smem + OFF_B + (uint32_t)(n * SROW + k8g * 8) * 2) = bsrc[idx];
            }
        }
        __syncthreads();

        float acc[2][8][4];
        #pragma unroll
        for (int mi = 0; mi < 2; mi++)
            #pragma unroll
            for (int nj = 0; nj < 8; nj++)
                #pragma unroll
                for (int e = 0; e < 4; e++) acc[mi][nj][e] = 0.f;

        #pragma unroll
        for (int ks = 0; ks < 8; ks++) {
            uint32_t ah[2][4];
            #pragma unroll
            for (int mi = 0; mi < 2; mi++) {
                uint32_t ad = sb + aoff + (uint32_t)(mi*16*SROW + ks*16) * 2;
                ldmatrix_x4(ah[mi], ad + OFF_A);
            }
            uint32_t bf[8][2];
            #pragma unroll
            for (int nj = 0; nj < 8; nj++) {
                uint32_t bd = sb + boff + (uint32_t)(nj*8*SROW + ks*16) * 2;
                ldmatrix_x2(bf[nj], bd + OFF_B);
            }
            #pragma unroll
            for (int mi = 0; mi < 2; mi++)
                #pragma unroll
                for (int nj = 0; nj < 8; nj++)
                    mma16816h(acc[mi][nj], ah[mi], bf[nj]);
        }

        // direct register epilogue (A stays resident in smem)
        const float* bt = (s == 0) ? (bq + l*TT*HIDD + t*128) : (d_bcomp + chunk*128);
        __half* dst;
        int stride;
        if (s == 0) { dst = d_qh + (size_t)base * 128; stride = 128; }
        else {
            int isV = (s-1) >> 2, r = (s-1) & 3;
            dst = d_kvrel + (size_t)base * 1024 + r*256 + isV*128;
            stride = 1024;
        }
        #pragma unroll
        for (int mi = 0; mi < 2; mi++) {
            #pragma unroll
            for (int nj = 0; nj < 8; nj++) {
                int row = wm*32 + mi*16 + (lane >> 2);
                int col = wn*64 + nj*8 + 2*(lane & 3);
                float b0 = __ldg(&bt[col]), b1 = __ldg(&bt[col+1]);
                __half2 h01 = __floats2half2_rn(acc[mi][nj][0] + b0, acc[mi][nj][1] + b1);
                __half2 h23 = __floats2half2_rn(acc[mi][nj][2] + b0, acc[mi][nj][3] + b1);
                *(__half2*)(dst + (size_t)row * stride + col)       = h01;
                *(__half2*)(dst + (size_t)(row+8) * stride + col)   = h23;
            }
        }
    }
}

// ---------------- edge phase: warp-per-dst, online softmax ---------------------
__device__ __forceinline__ void edge_step(uint2 kr, uint2 vr, const float4 q4,
                                          float& m, float& s, float4& acc) {
    const unsigned full = 0xffffffffu;
    float4 k4 = h4_to_f4(kr);
    float4 v4 = h4_to_f4(vr);
    float p = q4.x*k4.x + q4.y*k4.y + q4.z*k4.z + q4.w*k4.w;
    p += __shfl_xor_sync(full, p, 1);
    p += __shfl_xor_sync(full, p, 2);
    float mn = fmaxf(m, p);
    float corr = __expf(m - mn);
    float w = __expf(p - mn);
    s = s*corr + w;
    acc.x = fmaf(w, v4.x, acc.x*corr);
    acc.y = fmaf(w, v4.y, acc.y*corr);
    acc.z = fmaf(w, v4.z, acc.z*corr);
    acc.w = fmaf(w, v4.w, acc.w*corr);
    m = mn;
}

__global__ void k_edge() {
    const int n = (blockIdx.x*blockDim.x + threadIdx.x) >> 5;
    if (n >= NN) return;
    const int lane = threadIdx.x & 31;

    const int ip = d_iperm[n];
    float4 q4 = h4_to_f4(*(const uint2*)(d_qh + (size_t)ip*128 + lane*4));
    const int beg = d_off[n], end = d_off[n+1];

    float m = -1e30f, s = 0.f;
    float4 acc = make_float4(0.f,0.f,0.f,0.f);

    int e = beg;
    for (; e + 1 < end; e += 2) {
        int pk0 = d_epack[e], pk1 = d_epack[e+1];
        const __half* b0 = d_kvrel + (size_t)pk0*256;
        const __half* b1 = d_kvrel + (size_t)pk1*256;
        uint2 k0 = *(const uint2*)(b0 + lane*4);
        uint2 v0 = *(const uint2*)(b0 + 128 + lane*4);
        uint2 k1 = *(const uint2*)(b1 + lane*4);
        uint2 v1 = *(const uint2*)(b1 + 128 + lane*4);
        edge_step(k0, v0, q4, m, s, acc);
        edge_step(k1, v1, q4, m, s, acc);
    }
    if (e < end) {
        int pk0 = d_epack[e];
        const __half* b0 = d_kvrel + (size_t)pk0*256;
        uint2 k0 = *(const uint2*)(b0 + lane*4);
        uint2 v0 = *(const uint2*)(b0 + 128 + lane*4);
        edge_step(k0, v0, q4, m, s, acc);
    }
    float inv = 1.0f / fmaxf(s, 1e-9f);
    acc.x *= inv; acc.y *= inv; acc.z *= inv; acc.w *= inv;
    *(uint2*)(d_aggh + (size_t)ip*128 + lane*4) = f4_to_h4(acc);
}

// ---------------- launch --------------------------------------------------------
extern "C" void kernel_launch(void* const* d_in, const int* in_sizes, int n_in,
                              void* d_out, int out_size) {
    const float* x      = (const float*)d_in[0];
    const int*   ntypes = (const int*)d_in[1];
    const int*   ei     = (const int*)d_in[2];
    const int*   et     = (const int*)d_in[3];
    const float* Wad    = (const float*)d_in[4];
    const float* bad    = (const float*)d_in[5];
    const float* Wk     = (const float*)d_in[6];
    const float* bk     = (const float*)d_in[7];
    const float* Wq     = (const float*)d_in[8];
    const float* bq     = (const float*)d_in[9];
    const float* Wv     = (const float*)d_in[10];
    const float* bv     = (const float*)d_in[11];
    const float* Wa     = (const float*)d_in[12];
    const float* ba     = (const float*)d_in[13];
    const float* pri    = (const float*)d_in[14];
    const float* ratt   = (const float*)d_in[15];
    const float* rmsg   = (const float*)d_in[16];
    const float* skip   = (const float*)d_in[17];
    const float* gamma  = (const float*)d_in[18];
    const float* beta   = (const float*)d_in[19];
    float* out = (float*)d_out;

    const int* srcA = ei;
    const int* dstA = ei + EE;

    cudaFuncSetAttribute(k_gemm_adapt,   cudaFuncAttributeMaxDynamicSharedMemorySize, GSMEM);
    cudaFuncSetAttribute(k_gemm_qkv_all, cudaFuncAttributeMaxDynamicSharedMemorySize, GSMEM);
    cudaFuncSetAttribute(k_gemm_att0,    cudaFuncAttributeMaxDynamicSharedMemorySize, GSMEM);
    cudaFuncSetAttribute(k_gemm_att1,    cudaFuncAttributeMaxDynamicSharedMemorySize, GSMEM);

    const int SCAN_BLK = (NN + 255) / 256;
    const int WARP_BLK = (NN*32 + 255) / 256;

    k_init<<<(NP+255)/256, 256>>>();
    k_count<<<(EE+255)/256, 256>>>(ntypes, dstA);
    k_toffsets<<<1, 1>>>();
    k_scatter_nodes<<<(NN+255)/256, 256>>>(ntypes);
    k_scan1<<<SCAN_BLK, 256>>>();
    k_scan2<<<1, 256>>>(SCAN_BLK);
    k_scan3<<<SCAN_BLK, 256>>>();
    k_scatter_edges<<<(EE+255)/256, 256>>>(srcA, dstA, et);
    k_wprep<<<NCHUNKS, 256>>>(Wad, Wk, bk, Wq, Wv, bv, Wa, ratt, rmsg, pri);

    k_gemm_adapt<<<NTILE, 256, GSMEM>>>(x, bad);

    for (int l = 0; l < 2; l++) {
        int lbase = 6 + l*30;
        k_gemm_qkv_all<<<NTILE, 256, GSMEM>>>(l, bq);
        k_edge<<<WARP_BLK, 256>>>();
        if (l == 0) {
            k_gemm_att0<<<NTILE, 256, GSMEM>>>(lbase + 27, ba + l*TT*HIDD, skip + l*TT, gamma, beta);
        } else {
            k_gemm_att1<<<NTILE, 256, GSMEM>>>(lbase + 27, ba + l*TT*HIDD, skip + l*TT, out);
        }
    }
}

// round 9
// speedup vs baseline: 1.0583x; 1.0318x over previous
#include <cuda_runtime.h>
#include <cuda_fp16.h>
#include <cstdint>
#include <math.h>

#define NN   50000
#define EE   400000
#define IND  256
#define HIDD 128
#define TT   3
#define RR   4
#define HH   8
#define DKK  16
#define NP   50432          // 394 blocks * 128
#define NTILE 394
#define NCHUNKS 66          // 6 adapt + 2*(3 q + 24 composite + 3 att)

// ---------------- scratch (static device globals) -----------------------------
__device__ float d_h0[NP*HIDD];
__device__ float d_h1[NP*HIDD];
__device__ __half d_aggh[NP*HIDD];
__device__ __half d_qh[NP*HIDD];
__device__ __half d_kvrel[(size_t)NP*RR*256];   // [p*4+r][0:128]=krel*pri/4, [128:256]=vrel
__device__ __half d_wpack[NCHUNKS*16384];
__device__ float  d_bcomp[NCHUNKS*128];
__device__ int   d_deg[NN];
__device__ int   d_off[NN+1];
__device__ int   d_cursor[NN];
__device__ int   d_epack[EE];
__device__ int   d_bsum[256];
__device__ int   d_bpre[256];
__device__ int   d_tcnt[TT];
__device__ int   d_topad[TT+1];
__device__ int   d_tcur[TT];
__device__ int   d_nperm[NP];
__device__ int   d_iperm[NN];

// ---------------- helpers -------------------------------------------------------
__device__ __forceinline__ uint32_t smem_u32(const void* p) {
    uint32_t a;
    asm("{ .reg .u64 t; cvta.to.shared.u64 t, %1; cvt.u32.u64 %0, t; }" : "=r"(a) : "l"(p));
    return a;
}
__device__ __forceinline__ void ldmatrix_x4(uint32_t* r, uint32_t addr) {
    asm volatile("ldmatrix.sync.aligned.m8n8.x4.shared.b16 {%0,%1,%2,%3}, [%4];"
                 : "=r"(r[0]), "=r"(r[1]), "=r"(r[2]), "=r"(r[3]) : "r"(addr));
}
__device__ __forceinline__ void ldmatrix_x2(uint32_t* r, uint32_t addr) {
    asm volatile("ldmatrix.sync.aligned.m8n8.x2.shared.b16 {%0,%1}, [%2];"
                 : "=r"(r[0]), "=r"(r[1]) : "r"(addr));
}
__device__ __forceinline__ void mma16816h(float* d, const uint32_t* a, const uint32_t* b) {
    asm volatile("mma.sync.aligned.m16n8k16.row.col.f32.f16.f16.f32 "
                 "{%0,%1,%2,%3}, {%4,%5,%6,%7}, {%8,%9}, {%0,%1,%2,%3};"
                 : "+f"(d[0]), "+f"(d[1]), "+f"(d[2]), "+f"(d[3])
                 : "r"(a[0]), "r"(a[1]), "r"(a[2]), "r"(a[3]), "r"(b[0]), "r"(b[1]));
}
__device__ __forceinline__ float4 h4_to_f4(uint2 u) {
    __half2 a = *reinterpret_cast<__half2*>(&u.x);
    __half2 b = *reinterpret_cast<__half2*>(&u.y);
    float2 fa = __half22float2(a), fb = __half22float2(b);
    return make_float4(fa.x, fa.y, fb.x, fb.y);
}
__device__ __forceinline__ uint2 f4_to_h4(float4 f) {
    __half2 a = __floats2half2_rn(f.x, f.y);
    __half2 b = __floats2half2_rn(f.z, f.w);
    uint2 u;
    u.x = *reinterpret_cast<uint32_t*>(&a);
    u.y = *reinterpret_cast<uint32_t*>(&b);
    return u;
}

// ---------------- setup kernels ------------------------------------------------
__global__ void k_init() {
    int i = blockIdx.x*blockDim.x + threadIdx.x;
    if (i < NP) d_nperm[i] = -1;
    if (i < NN) d_deg[i] = 0;
    if (i < TT) d_tcnt[i] = 0;
}
__global__ void k_count(const int* __restrict__ ntypes, const int* __restrict__ dst) {
    __shared__ int sh[TT];
    if (threadIdx.x < TT) sh[threadIdx.x] = 0;
    __syncthreads();
    int i = blockIdx.x*blockDim.x + threadIdx.x;
    if (i < NN) atomicAdd(&sh[ntypes[i]], 1);
    if (i < EE) atomicAdd(&d_deg[dst[i]], 1);
    __syncthreads();
    if (threadIdx.x < TT && sh[threadIdx.x]) atomicAdd(&d_tcnt[threadIdx.x], sh[threadIdx.x]);
}
__global__ void k_toffsets() {
    int run = 0;
    for (int t = 0; t < TT; t++) {
        d_topad[t] = run; d_tcur[t] = run;
        run += ((d_tcnt[t] + 127) / 128) * 128;
    }
    d_topad[TT] = run;
}
__global__ void k_scatter_nodes(const int* __restrict__ ntypes) {
    __shared__ int scnt[TT], sbase[TT];
    if (threadIdx.x < TT) scnt[threadIdx.x] = 0;
    __syncthreads();
    int i = blockIdx.x*blockDim.x + threadIdx.x;
    int t = 0, myidx = 0;
    bool valid = (i < NN);
    if (valid) { t = ntypes[i]; myidx = atomicAdd(&scnt[t], 1); }
    __syncthreads();
    if (threadIdx.x < TT) sbase[threadIdx.x] = atomicAdd(&d_tcur[threadIdx.x], scnt[threadIdx.x]);
    __syncthreads();
    if (valid) {
        int p = sbase[t] + myidx;
        d_nperm[p] = i;
        d_iperm[i] = p;
    }
}
__device__ __forceinline__ int block_scan_incl(int x, int* wsum) {
    unsigned full = 0xffffffffu;
    int lane = threadIdx.x & 31, wid = threadIdx.x >> 5;
    int v = x;
    #pragma unroll
    for (int d = 1; d < 32; d <<= 1) {
        int t = __shfl_up_sync(full, v, d);
        if (lane >= d) v += t;
    }
    if (lane == 31) wsum[wid] = v;
    __syncthreads();
    if (threadIdx.x == 0) {
        int run = 0;
        #pragma unroll
        for (int w = 0; w < 8; w++) { int t = wsum[w]; wsum[w] = run; run += t; }
    }
    __syncthreads();
    return v + wsum[wid];
}
__global__ void k_scan1() {
    __shared__ int wsum[8];
    int i = blockIdx.x*256 + threadIdx.x;
    int x = (i < NN) ? d_deg[i] : 0;
    int inc = block_scan_incl(x, wsum);
    if (i < NN) d_off[i] = inc - x;
    if (threadIdx.x == 255) d_bsum[blockIdx.x] = inc;
}
__global__ void k_scan2(int nblocks) {
    __shared__ int wsum[8];
    int t = threadIdx.x;
    int x = (t < nblocks) ? d_bsum[t] : 0;
    int inc = block_scan_incl(x, wsum);
    d_bpre[t] = inc - x;
}
__global__ void k_scan3() {
    int i = blockIdx.x*256 + threadIdx.x;
    if (i < NN) {
        int v = d_off[i] + d_bpre[i >> 8];
        d_off[i] = v; d_cursor[i] = v;
    }
    if (i == 0) d_off[NN] = EE;
}
__global__ void k_scatter_edges(const int* __restrict__ src, const int* __restrict__ dst,
                                const int* __restrict__ et) {
    int e = blockIdx.x*blockDim.x + threadIdx.x;
    if (e < EE) {
        int pos = atomicAdd(&d_cursor[dst[e]], 1);
        d_epack[pos] = (d_iperm[src[e]] << 2) | et[e];
    }
}

// ---------------- weight pack: plain + composite chunks -------------------------
// chunk map: 0..5 adapt (t=c>>1, khalf=c&1)
// per layer l at base 6+l*30: s=0..2 q(t=s); s=3..26 composite
//   (sc=s-3: isV=sc/12, r=(sc%12)/3, t=sc%3); s=27..29 att(t=s-27)
__global__ void k_wprep(const float* __restrict__ Wad,
                        const float* __restrict__ Wk, const float* __restrict__ bk,
                        const float* __restrict__ Wq,
                        const float* __restrict__ Wv, const float* __restrict__ bv,
                        const float* __restrict__ Wa,
                        const float* __restrict__ Ratt, const float* __restrict__ Rmsg,
                        const float* __restrict__ pri) {
    int c = blockIdx.x;
    int tid = threadIdx.x;
    __half* oh = d_wpack + (size_t)c * 16384;

    if (c < 6) {
        int t = c >> 1, k0 = (c & 1) * 128;
        const float* W = Wad + (size_t)t * 256 * 128;
        for (int i = tid; i < 16384; i += 256) {
            int n = i >> 7, k = i & 127;
            oh[n*128 + k] = __float2half_rn(W[(size_t)(k0 + k) * 128 + n]);
        }
        return;
    }
    int cc = c - 6, l = cc / 30, s = cc % 30;
    if (s < 3 || s >= 27) {
        const float* W = (s < 3) ? (Wq + (size_t)(l*3 + s) * 16384)
                                 : (Wa + (size_t)(l*3 + (s-27)) * 16384);
        for (int i = tid; i < 16384; i += 256) {
            int n = i >> 7, k = i & 127;
            oh[n*128 + k] = __float2half_rn(W[(size_t)k * 128 + n]);
        }
        return;
    }
    // composite
    int sc = s - 3;
    int isV = sc / 12, rem = sc % 12, r = rem / 3, t = rem % 3;
    const float* Ws = (isV ? Wv : Wk) + (size_t)(l*3 + t) * 16384;
    const float* Rm = (isV ? Rmsg : Ratt) + (size_t)(l*RR + r) * HH * 256;  // [h][d][f]
    const float* bs = (isV ? bv : bk) + (l*3 + t) * 128;
    for (int i = tid; i < 16384; i += 256) {
        int n = i >> 7, k = i & 127;
        int h = n >> 4, f = n & 15;
        const float* wrow = Ws + (size_t)k * 128 + h * 16;
        const float* rcol = Rm + h * 256 + f;
        float acc = 0.f;
        #pragma unroll
        for (int d = 0; d < 16; d++) acc = fmaf(wrow[d], rcol[d*16], acc);
        float ps = isV ? 1.0f : (__ldg(&pri[l*RR*HH + r*HH + h]) * 0.25f);
        oh[n*128 + k] = __float2half_rn(acc * ps);
    }
    if (tid < 128) {
        int n = tid, h = n >> 4, f = n & 15;
        const float* rcol = Rm + h * 256 + f;
        float acc = 0.f;
        #pragma unroll
        for (int d = 0; d < 16; d++) acc = fmaf(bs[h*16 + d], rcol[d*16], acc);
        float ps = isV ? 1.0f : (__ldg(&pri[l*RR*HH + r*HH + h]) * 0.25f);
        d_bcomp[c*128 + n] = acc * ps;
    }
}

// ---------------- smem layout ----------------------------------------------------
#define SROW   136
#define OFF_A  0
#define OFF_B  34816
#define GSMEM  69632

// ---------------- generic GEMM core (adapt / att) --------------------------------
// GATHER: 1 gather fp32 rows via nperm, 3 contiguous fp16 + GELU
// EPI: 1 tanh->f32(outf), 3 combine1(LN+ReLU->d_h1), 4 combine2(->outfinal via nperm)
template<int GATHER, int EPI>
__device__ __forceinline__ void gemm_core(const void* __restrict__ Av, int nch, int cbase,
                                          const float* __restrict__ bias,
                                          float* __restrict__ outf,
                                          const float* __restrict__ hx,
                                          const float* __restrict__ skip,
                                          const float* __restrict__ gamma,
                                          const float* __restrict__ beta,
                                          float* __restrict__ outfinal) {
    extern __shared__ char smem[];
    const uint32_t sb = smem_u32(smem);
    const int tid = threadIdx.x;
    const int wid = tid >> 5, lane = tid & 31;
    const int base = blockIdx.x * 128;
    const int t = (base >= d_topad[1]) + (base >= d_topad[2]);
    const float* bt = bias + t * 128;
    const int lda = nch * 128;
    const int wm = wid & 3, wn = wid >> 2;

    float acc[2][8][4];
    #pragma unroll
    for (int mi = 0; mi < 2; mi++)
        #pragma unroll
        for (int nj = 0; nj < 8; nj++)
            #pragma unroll
            for (int e = 0; e < 4; e++) acc[mi][nj][e] = 0.f;

    const uint32_t aoff = (uint32_t)((wm*32 + (lane & 15)) * SROW + (lane >> 4) * 8) * 2;
    const int l16 = lane & 15;
    const uint32_t boff = (uint32_t)((wn*64 + (l16 & 7)) * SROW + (l16 >> 3) * 8) * 2;

    for (int kc = 0; kc < nch; kc++) {
        if (kc > 0) __syncthreads();
        {
            int chunk = cbase + t * nch + kc;
            const uint4* bsrc = (const uint4*)(d_wpack + (size_t)chunk * 16384);
            #pragma unroll
            for (int i = 0; i < 8; i++) {
                int idx = tid + i * 256;
                int n = idx >> 4, k8g = idx & 15;
                uint32_t doff = (uint32_t)(n * SROW + k8g * 8) * 2;
                *(uint4*)(smem + OFF_B + doff) = bsrc[idx];
            }
        }
        #pragma unroll
        for (int i = 0; i < 8; i++) {
            int gi = tid + i * 256;
            int row = gi >> 4;
            int k8 = (gi & 15) * 8;
            if (GATHER == 1) {
                const float* A = (const float*)Av;
                float v[8];
                int rn = d_nperm[base + row];
                if (rn >= 0) {
                    const float4* ap = (const float4*)(A + (size_t)rn * lda + kc*128 + k8);
                    float4 a0 = ap[0], a1 = ap[1];
                    v[0]=a0.x; v[1]=a0.y; v[2]=a0.z; v[3]=a0.w;
                    v[4]=a1.x; v[5]=a1.y; v[6]=a1.z; v[7]=a1.w;
                } else {
                    #pragma unroll
                    for (int j = 0; j < 8; j++) v[j] = 0.f;
                }
                union { __half b[8]; uint4 u; } ph;
                #pragma unroll
                for (int j = 0; j < 8; j++) ph.b[j] = __float2half_rn(v[j]);
                *(uint4*)(smem + OFF_A + (uint32_t)(row * SROW + k8) * 2) = ph.u;
            } else {
                const __half* A = (const __half*)Av;
                uint4 raw = *(const uint4*)(A + (size_t)(base + row) * 128 + k8);
                union { __half b[8]; uint4 u; } ph;
                const __half2* hp = reinterpret_cast<const __half2*>(&raw);
                #pragma unroll
                for (int j = 0; j < 4; j++) {
                    float2 f2 = __half22float2(hp[j]);
                    f2.x = 0.5f * f2.x * (1.0f + erff(f2.x * 0.70710678118654752f));
                    f2.y = 0.5f * f2.y * (1.0f + erff(f2.y * 0.70710678118654752f));
                    ph.b[2*j]   = __float2half_rn(f2.x);
                    ph.b[2*j+1] = __float2half_rn(f2.y);
                }
                *(uint4*)(smem + OFF_A + (uint32_t)(row * SROW + k8) * 2) = ph.u;
            }
        }
        __syncthreads();

        #pragma unroll
        for (int ks = 0; ks < 8; ks++) {
            uint32_t ah[2][4];
            #pragma unroll
            for (int mi = 0; mi < 2; mi++) {
                uint32_t ad = sb + aoff + (uint32_t)(mi*16*SROW + ks*16) * 2;
                ldmatrix_x4(ah[mi], ad + OFF_A);
            }
            uint32_t bf[8][2];
            #pragma unroll
            for (int nj = 0; nj < 8; nj++) {
                uint32_t bd = sb + boff + (uint32_t)(nj*8*SROW + ks*16) * 2;
                ldmatrix_x2(bf[nj], bd + OFF_B);
            }
            #pragma unroll
            for (int mi = 0; mi < 2; mi++)
                #pragma unroll
                for (int nj = 0; nj < 8; nj++)
                    mma16816h(acc[mi][nj], ah[mi], bf[nj]);
        }
    }
    __syncthreads();

    float* stage = (float*)smem;              // [128][132]
    #pragma unroll
    for (int mi = 0; mi < 2; mi++) {
        #pragma unroll
        for (int nj = 0; nj < 8; nj++) {
            int row = wm*32 + mi*16 + (lane >> 2);
            int col = wn*64 + nj*8 + 2*(lane & 3);
            float b0 = __ldg(&bt[col]), b1 = __ldg(&bt[col+1]);
            float v0 = acc[mi][nj][0] + b0;
            float v1 = acc[mi][nj][1] + b1;
            float v2 = acc[mi][nj][2] + b0;
            float v3 = acc[mi][nj][3] + b1;
            if (EPI == 1) { v0 = tanhf(v0); v1 = tanhf(v1); v2 = tanhf(v2); v3 = tanhf(v3); }
            stage[row*132 + col]     = v0;
            stage[row*132 + col + 1] = v1;
            stage[(row+8)*132 + col]     = v2;
            stage[(row+8)*132 + col + 1] = v3;
        }
    }
    __syncthreads();

    if (EPI == 1) {
        for (int i = tid; i < 4096; i += 256) {
            int row = i >> 5, c4 = i & 31;
            *(float4*)(outf + ((size_t)(base + row)) * 128 + c4 * 4) =
                *(const float4*)(stage + row * 132 + c4 * 4);
        }
    } else {
        const unsigned full = 0xffffffffu;
        float alpha = 1.0f / (1.0f + __expf(-__ldg(&skip[t])));
        float ia = 1.0f - alpha;
        float4 g4, b4;
        if (EPI == 3) {
            g4 = *(const float4*)(gamma + t*128 + lane*4);
            b4 = *(const float4*)(beta  + t*128 + lane*4);
        }
        #pragma unroll
        for (int i = 0; i < 16; i++) {
            int row = wid*16 + i;
            float4 tr = *(const float4*)(stage + row*132 + lane*4);
            float4 hx4 = *(const float4*)(hx + (size_t)(base+row)*128 + lane*4);
            float4 o;
            o.x = tr.x*alpha + hx4.x*ia;
            o.y = tr.y*alpha + hx4.y*ia;
            o.z = tr.z*alpha + hx4.z*ia;
            o.w = tr.w*alpha + hx4.w*ia;
            if (EPI == 3) {
                float sm = o.x + o.y + o.z + o.w;
                float sq = o.x*o.x + o.y*o.y + o.z*o.z + o.w*o.w;
                #pragma unroll
                for (int d = 16; d; d >>= 1) {
                    sm += __shfl_xor_sync(full, sm, d);
                    sq += __shfl_xor_sync(full, sq, d);
                }
                float mean = sm * (1.0f/128.0f);
                float var  = sq * (1.0f/128.0f) - mean*mean;
                float rstd = rsqrtf(var + 1e-5f);
                float4 y;
                y.x = fmaxf((o.x-mean)*rstd*g4.x + b4.x, 0.f);
                y.y = fmaxf((o.y-mean)*rstd*g4.y + b4.y, 0.f);
                y.z = fmaxf((o.z-mean)*rstd*g4.z + b4.z, 0.f);
                y.w = fmaxf((o.w-mean)*rstd*g4.w + b4.w, 0.f);
                *(float4*)(d_h1 + (size_t)(base+row)*128 + lane*4) = y;
            } else {
                int node = d_nperm[base + row];
                if (node >= 0)
                    *(float4*)(outfinal + (size_t)node*128 + lane*4) = o;
            }
        }
    }
}

__global__ void __launch_bounds__(256,2)
k_gemm_adapt(const float* __restrict__ x, const float* __restrict__ bad) {
    gemm_core<1,1>(x, 2, 0, bad, d_h0, nullptr, nullptr, nullptr, nullptr, nullptr);
}
__global__ void __launch_bounds__(256,2)
k_gemm_att0(int cb, const float* __restrict__ ba, const float* __restrict__ skip,
            const float* __restrict__ gamma, const float* __restrict__ beta) {
    gemm_core<3,3>(d_aggh, 1, cb, ba, nullptr, d_h0, skip, gamma, beta, nullptr);
}
__global__ void __launch_bounds__(256,2)
k_gemm_att1(int cb, const float* __restrict__ ba, const float* __restrict__ skip,
            float* __restrict__ out) {
    gemm_core<3,4>(d_aggh, 1, cb, ba, nullptr, d_h1, skip, nullptr, nullptr, out);
}

// ---------------- fused q + 8x kvrel GEMM: A staged ONCE, loop over 9 B's --------
// Epilogue stages fp16 results in the (dead) B smem region, then does coalesced
// 16B-per-thread global writes (fixes the 2x write amplification of direct
// fragment stores).
__global__ void __launch_bounds__(256,2)
k_gemm_qkv_all(int l, const float* __restrict__ bq) {
    extern __shared__ char smem[];
    const uint32_t sb = smem_u32(smem);
    const int tid = threadIdx.x;
    const int wid = tid >> 5, lane = tid & 31;
    const int base = blockIdx.x * 128;
    const int t = (base >= d_topad[1]) + (base >= d_topad[2]);
    const float* A = l ? d_h1 : d_h0;
    const int lbase = 6 + l*30;
    const int wm = wid & 3, wn = wid >> 2;

    // stage A (fp32 -> fp16) once
    #pragma unroll
    for (int i = 0; i < 8; i++) {
        int gi = tid + i * 256;
        int row = gi >> 4;
        int k8 = (gi & 15) * 8;
        const float4* ap = (const float4*)(A + (size_t)(base + row) * 128 + k8);
        float4 a0 = ap[0], a1 = ap[1];
        union { __half b[8]; uint4 u; } ph;
        ph.b[0]=__float2half_rn(a0.x); ph.b[1]=__float2half_rn(a0.y);
        ph.b[2]=__float2half_rn(a0.z); ph.b[3]=__float2half_rn(a0.w);
        ph.b[4]=__float2half_rn(a1.x); ph.b[5]=__float2half_rn(a1.y);
        ph.b[6]=__float2half_rn(a1.z); ph.b[7]=__float2half_rn(a1.w);
        *(uint4*)(smem + OFF_A + (uint32_t)(row * SROW + k8) * 2) = ph.u;
    }

    const uint32_t aoff = (uint32_t)((wm*32 + (lane & 15)) * SROW + (lane >> 4) * 8) * 2;
    const int l16 = lane & 15;
    const uint32_t boff = (uint32_t)((wn*64 + (l16 & 7)) * SROW + (l16 >> 3) * 8) * 2;

    for (int s = 0; s < 9; s++) {
        __syncthreads();   // A/B stage writes visible; previous epilogue reads done
        int chunk = (s == 0) ? (lbase + t)
                             : (lbase + 3 + (((s-1) >> 2) * 12) + (((s-1) & 3) * 3) + t);
        {
            const uint4* bsrc = (const uint4*)(d_wpack + (size_t)chunk * 16384);
            #pragma unroll
            for (int i = 0; i < 8; i++) {
                int idx = tid + i * 256;
                int n = idx >> 4, k8g = idx & 15;
                *(uint4*)(smem + OFF_B + (uint32_t)(n * SROW + k8g * 8) * 2) = bsrc[idx];
            }
        }
        __syncthreads();

        float acc[2][8][4];
        #pragma unroll
        for (int mi = 0; mi < 2; mi++)
            #pragma unroll
            for (int nj = 0; nj < 8; nj++)
                #pragma unroll
                for (int e = 0; e < 4; e++) acc[mi][nj][e] = 0.f;

        #pragma unroll
        for (int ks = 0; ks < 8; ks++) {
            uint32_t ah[2][4];
            #pragma unroll
            for (int mi = 0; mi < 2; mi++) {
                uint32_t ad = sb + aoff + (uint32_t)(mi*16*SROW + ks*16) * 2;
                ldmatrix_x4(ah[mi], ad + OFF_A);
            }
            uint32_t bf[8][2];
            #pragma unroll
            for (int nj = 0; nj < 8; nj++) {
                uint32_t bd = sb + boff + (uint32_t)(nj*8*SROW + ks*16) * 2;
                ldmatrix_x2(bf[nj], bd + OFF_B);
            }
            #pragma unroll
            for (int mi = 0; mi < 2; mi++)
                #pragma unroll
                for (int nj = 0; nj < 8; nj++)
                    mma16816h(acc[mi][nj], ah[mi], bf[nj]);
        }
        __syncthreads();   // all B ldmatrix reads done; B region now reusable as stage

        // stage fp16 results into B region
        const float* bt = (s == 0) ? (bq + l*TT*HIDD + t*128) : (d_bcomp + chunk*128);
        __half* hstage = (__half*)(smem + OFF_B);
        #pragma unroll
        for (int mi = 0; mi < 2; mi++) {
            #pragma unroll
            for (int nj = 0; nj < 8; nj++) {
                int row = wm*32 + mi*16 + (lane >> 2);
                int col = wn*64 + nj*8 + 2*(lane & 3);
                float b0 = __ldg(&bt[col]), b1 = __ldg(&bt[col+1]);
                __half2 h01 = __floats2half2_rn(acc[mi][nj][0] + b0, acc[mi][nj][1] + b1);
                __half2 h23 = __floats2half2_rn(acc[mi][nj][2] + b0, acc[mi][nj][3] + b1);
                *(__half2*)(hstage + row * SROW + col)     = h01;
                *(__half2*)(hstage + (row+8) * SROW + col) = h23;
            }
        }
        __syncthreads();

        // coalesced global write: 16B per thread, 256B contiguous per row
        __half* dst;
        int stride;
        if (s == 0) { dst = d_qh + (size_t)base * 128; stride = 128; }
        else {
            int isV = (s-1) >> 2, r = (s-1) & 3;
            dst = d_kvrel + (size_t)base * 1024 + r*256 + isV*128;
            stride = 1024;
        }
        #pragma unroll
        for (int i = 0; i < 8; i++) {
            int idx = tid + i * 256;
            int row = idx >> 4, seg = idx & 15;
            uint4 v = *(const uint4*)(hstage + row * SROW + seg * 8);
            *(uint4*)(dst + (size_t)row * stride + seg * 8) = v;
        }
    }
}

// ---------------- edge phase: warp-per-dst, online softmax ---------------------
__device__ __forceinline__ void edge_step(uint2 kr, uint2 vr, const float4 q4,
                                          float& m, float& s, float4& acc) {
    const unsigned full = 0xffffffffu;
    float4 k4 = h4_to_f4(kr);
    float4 v4 = h4_to_f4(vr);
    float p = q4.x*k4.x + q4.y*k4.y + q4.z*k4.z + q4.w*k4.w;
    p += __shfl_xor_sync(full, p, 1);
    p += __shfl_xor_sync(full, p, 2);
    float mn = fmaxf(m, p);
    float corr = __expf(m - mn);
    float w = __expf(p - mn);
    s = s*corr + w;
    acc.x = fmaf(w, v4.x, acc.x*corr);
    acc.y = fmaf(w, v4.y, acc.y*corr);
    acc.z = fmaf(w, v4.z, acc.z*corr);
    acc.w = fmaf(w, v4.w, acc.w*corr);
    m = mn;
}

__global__ void k_edge() {
    const int n = (blockIdx.x*blockDim.x + threadIdx.x) >> 5;
    if (n >= NN) return;
    const int lane = threadIdx.x & 31;

    const int ip = d_iperm[n];
    float4 q4 = h4_to_f4(*(const uint2*)(d_qh + (size_t)ip*128 + lane*4));
    const int beg = d_off[n], end = d_off[n+1];

    float m = -1e30f, s = 0.f;
    float4 acc = make_float4(0.f,0.f,0.f,0.f);

    int e = beg;
    for (; e + 1 < end; e += 2) {
        int pk0 = d_epack[e], pk1 = d_epack[e+1];
        const __half* b0 = d_kvrel + (size_t)pk0*256;
        const __half* b1 = d_kvrel + (size_t)pk1*256;
        uint2 k0 = *(const uint2*)(b0 + lane*4);
        uint2 v0 = *(const uint2*)(b0 + 128 + lane*4);
        uint2 k1 = *(const uint2*)(b1 + lane*4);
        uint2 v1 = *(const uint2*)(b1 + 128 + lane*4);
        edge_step(k0, v0, q4, m, s, acc);
        edge_step(k1, v1, q4, m, s, acc);
    }
    if (e < end) {
        int pk0 = d_epack[e];
        const __half* b0 = d_kvrel + (size_t)pk0*256;
        uint2 k0 = *(const uint2*)(b0 + lane*4);
        uint2 v0 = *(const uint2*)(b0 + 128 + lane*4);
        edge_step(k0, v0, q4, m, s, acc);
    }
    float inv = 1.0f / fmaxf(s, 1e-9f);
    acc.x *= inv; acc.y *= inv; acc.z *= inv; acc.w *= inv;
    *(uint2*)(d_aggh + (size_t)ip*128 + lane*4) = f4_to_h4(acc);
}

// ---------------- launch --------------------------------------------------------
extern "C" void kernel_launch(void* const* d_in, const int* in_sizes, int n_in,
                              void* d_out, int out_size) {
    const float* x      = (const float*)d_in[0];
    const int*   ntypes = (const int*)d_in[1];
    const int*   ei     = (const int*)d_in[2];
    const int*   et     = (const int*)d_in[3];
    const float* Wad    = (const float*)d_in[4];
    const float* bad    = (const float*)d_in[5];
    const float* Wk     = (const float*)d_in[6];
    const float* bk     = (const float*)d_in[7];
    const float* Wq     = (const float*)d_in[8];
    const float* bq     = (const float*)d_in[9];
    const float* Wv     = (const float*)d_in[10];
    const float* bv     = (const float*)d_in[11];
    const float* Wa     = (const float*)d_in[12];
    const float* ba     = (const float*)d_in[13];
    const float* pri    = (const float*)d_in[14];
    const float* ratt   = (const float*)d_in[15];
    const float* rmsg   = (const float*)d_in[16];
    const float* skip   = (const float*)d_in[17];
    const float* gamma  = (const float*)d_in[18];
    const float* beta   = (const float*)d_in[19];
    float* out = (float*)d_out;

    const int* srcA = ei;
    const int* dstA = ei + EE;

    cudaFuncSetAttribute(k_gemm_adapt,   cudaFuncAttributeMaxDynamicSharedMemorySize, GSMEM);
    cudaFuncSetAttribute(k_gemm_qkv_all, cudaFuncAttributeMaxDynamicSharedMemorySize, GSMEM);
    cudaFuncSetAttribute(k_gemm_att0,    cudaFuncAttributeMaxDynamicSharedMemorySize, GSMEM);
    cudaFuncSetAttribute(k_gemm_att1,    cudaFuncAttributeMaxDynamicSharedMemorySize, GSMEM);

    const int SCAN_BLK = (NN + 255) / 256;
    const int WARP_BLK = (NN*32 + 255) / 256;

    k_init<<<(NP+255)/256, 256>>>();
    k_count<<<(EE+255)/256, 256>>>(ntypes, dstA);
    k_toffsets<<<1, 1>>>();
    k_scatter_nodes<<<(NN+255)/256, 256>>>(ntypes);
    k_scan1<<<SCAN_BLK, 256>>>();
    k_scan2<<<1, 256>>>(SCAN_BLK);
    k_scan3<<<SCAN_BLK, 256>>>();
    k_scatter_edges<<<(EE+255)/256, 256>>>(srcA, dstA, et);
    k_wprep<<<NCHUNKS, 256>>>(Wad, Wk, bk, Wq, Wv, bv, Wa, ratt, rmsg, pri);

    k_gemm_adapt<<<NTILE, 256, GSMEM>>>(x, bad);

    for (int l = 0; l < 2; l++) {
        int lbase = 6 + l*30;
        k_gemm_qkv_all<<<NTILE, 256, GSMEM>>>(l, bq);
        k_edge<<<WARP_BLK, 256>>>();
        if (l == 0) {
            k_gemm_att0<<<NTILE, 256, GSMEM>>>(lbase + 27, ba + l*TT*HIDD, skip + l*TT, gamma, beta);
        } else {
            k_gemm_att1<<<NTILE, 256, GSMEM>>>(lbase + 27, ba + l*TT*HIDD, skip + l*TT, out);
        }
    }
}

// round 10
// speedup vs baseline: 1.2602x; 1.1908x over previous
#include <cuda_runtime.h>
#include <cuda_fp16.h>
#include <cstdint>
#include <math.h>

#define NN   50000
#define EE   400000
#define IND  256
#define HIDD 128
#define TT   3
#define RR   4
#define HH   8
#define DKK  16
#define NP   50432          // 394 blocks * 128
#define NTILE 394
#define NCHUNKS 30          // 6 adapt + 2*(3k + 3q + 3v + 3att)

// ---------------- scratch (static device globals) -----------------------------
__device__ float d_h0[NP*HIDD];
__device__ float d_h1[NP*HIDD];
__device__ __half d_aggh[NP*HIDD];
__device__ __half d_kh[NP*HIDD];
__device__ __half d_qh[NP*HIDD];
__device__ __half d_vh[NP*HIDD];
__device__ __half d_kvrel[(size_t)NP*RR*256];   // [p*4+r][0:128]=krel*pri/4, [128:256]=vrel
__device__ __half d_wpack[NCHUNKS*16384];
__device__ int   d_deg[NN];
__device__ int   d_off[NN+1];
__device__ int   d_cursor[NN];
__device__ int   d_epack[EE];
__device__ int   d_bsum[256];
__device__ int   d_bpre[256];
__device__ int   d_tcnt[TT];
__device__ int   d_topad[TT+1];
__device__ int   d_tcur[TT];
__device__ int   d_nperm[NP];
__device__ int   d_iperm[NN];

// ---------------- helpers -------------------------------------------------------
__device__ __forceinline__ uint32_t smem_u32(const void* p) {
    uint32_t a;
    asm("{ .reg .u64 t; cvta.to.shared.u64 t, %1; cvt.u32.u64 %0, t; }" : "=r"(a) : "l"(p));
    return a;
}
__device__ __forceinline__ void ldmatrix_x4(uint32_t* r, uint32_t addr) {
    asm volatile("ldmatrix.sync.aligned.m8n8.x4.shared.b16 {%0,%1,%2,%3}, [%4];"
                 : "=r"(r[0]), "=r"(r[1]), "=r"(r[2]), "=r"(r[3]) : "r"(addr));
}
__device__ __forceinline__ void ldmatrix_x2(uint32_t* r, uint32_t addr) {
    asm volatile("ldmatrix.sync.aligned.m8n8.x2.shared.b16 {%0,%1}, [%2];"
                 : "=r"(r[0]), "=r"(r[1]) : "r"(addr));
}
__device__ __forceinline__ void mma16816h(float* d, const uint32_t* a, const uint32_t* b) {
    asm volatile("mma.sync.aligned.m16n8k16.row.col.f32.f16.f16.f32 "
                 "{%0,%1,%2,%3}, {%4,%5,%6,%7}, {%8,%9}, {%0,%1,%2,%3};"
                 : "+f"(d[0]), "+f"(d[1]), "+f"(d[2]), "+f"(d[3])
                 : "r"(a[0]), "r"(a[1]), "r"(a[2]), "r"(a[3]), "r"(b[0]), "r"(b[1]));
}
__device__ __forceinline__ float4 h4_to_f4(uint2 u) {
    __half2 a = *reinterpret_cast<__half2*>(&u.x);
    __half2 b = *reinterpret_cast<__half2*>(&u.y);
    float2 fa = __half22float2(a), fb = __half22float2(b);
    return make_float4(fa.x, fa.y, fb.x, fb.y);
}
__device__ __forceinline__ uint2 f4_to_h4(float4 f) {
    __half2 a = __floats2half2_rn(f.x, f.y);
    __half2 b = __floats2half2_rn(f.z, f.w);
    uint2 u;
    u.x = *reinterpret_cast<uint32_t*>(&a);
    u.y = *reinterpret_cast<uint32_t*>(&b);
    return u;
}

// ---------------- setup kernels ------------------------------------------------
__global__ void k_init() {
    int i = blockIdx.x*blockDim.x + threadIdx.x;
    if (i < NP) d_nperm[i] = -1;
    if (i < NN) d_deg[i] = 0;
    if (i < TT) d_tcnt[i] = 0;
}
__global__ void k_count(const int* __restrict__ ntypes, const int* __restrict__ dst) {
    __shared__ int sh[TT];
    if (threadIdx.x < TT) sh[threadIdx.x] = 0;
    __syncthreads();
    int i = blockIdx.x*blockDim.x + threadIdx.x;
    if (i < NN) atomicAdd(&sh[ntypes[i]], 1);
    if (i < EE) atomicAdd(&d_deg[dst[i]], 1);
    __syncthreads();
    if (threadIdx.x < TT && sh[threadIdx.x]) atomicAdd(&d_tcnt[threadIdx.x], sh[threadIdx.x]);
}
__global__ void k_toffsets() {
    int run = 0;
    for (int t = 0; t < TT; t++) {
        d_topad[t] = run; d_tcur[t] = run;
        run += ((d_tcnt[t] + 127) / 128) * 128;
    }
    d_topad[TT] = run;
}
__global__ void k_scatter_nodes(const int* __restrict__ ntypes) {
    __shared__ int scnt[TT], sbase[TT];
    if (threadIdx.x < TT) scnt[threadIdx.x] = 0;
    __syncthreads();
    int i = blockIdx.x*blockDim.x + threadIdx.x;
    int t = 0, myidx = 0;
    bool valid = (i < NN);
    if (valid) { t = ntypes[i]; myidx = atomicAdd(&scnt[t], 1); }
    __syncthreads();
    if (threadIdx.x < TT) sbase[threadIdx.x] = atomicAdd(&d_tcur[threadIdx.x], scnt[threadIdx.x]);
    __syncthreads();
    if (valid) {
        int p = sbase[t] + myidx;
        d_nperm[p] = i;
        d_iperm[i] = p;
    }
}
__device__ __forceinline__ int block_scan_incl(int x, int* wsum) {
    unsigned full = 0xffffffffu;
    int lane = threadIdx.x & 31, wid = threadIdx.x >> 5;
    int v = x;
    #pragma unroll
    for (int d = 1; d < 32; d <<= 1) {
        int t = __shfl_up_sync(full, v, d);
        if (lane >= d) v += t;
    }
    if (lane == 31) wsum[wid] = v;
    __syncthreads();
    if (threadIdx.x == 0) {
        int run = 0;
        #pragma unroll
        for (int w = 0; w < 8; w++) { int t = wsum[w]; wsum[w] = run; run += t; }
    }
    __syncthreads();
    return v + wsum[wid];
}
__global__ void k_scan1() {
    __shared__ int wsum[8];
    int i = blockIdx.x*256 + threadIdx.x;
    int x = (i < NN) ? d_deg[i] : 0;
    int inc = block_scan_incl(x, wsum);
    if (i < NN) d_off[i] = inc - x;
    if (threadIdx.x == 255) d_bsum[blockIdx.x] = inc;
}
__global__ void k_scan2(int nblocks) {
    __shared__ int wsum[8];
    int t = threadIdx.x;
    int x = (t < nblocks) ? d_bsum[t] : 0;
    int inc = block_scan_incl(x, wsum);
    d_bpre[t] = inc - x;
}
__global__ void k_scan3() {
    int i = blockIdx.x*256 + threadIdx.x;
    if (i < NN) {
        int v = d_off[i] + d_bpre[i >> 8];
        d_off[i] = v; d_cursor[i] = v;
    }
    if (i == 0) d_off[NN] = EE;
}
__global__ void k_scatter_edges(const int* __restrict__ src, const int* __restrict__ dst,
                                const int* __restrict__ et) {
    int e = blockIdx.x*blockDim.x + threadIdx.x;
    if (e < EE) {
        int pos = atomicAdd(&d_cursor[dst[e]], 1);
        d_epack[pos] = (d_iperm[src[e]] << 2) | et[e];
    }
}

// ---------------- weight pack: fp32 -> transposed fp16 --------------------------
// chunk c<6: adapt type t=c/2, k-half (c&1). chunks 6..29: layer l, g(k,q,v,a), type t.
__global__ void k_wprep(const float* __restrict__ Wad, const float* __restrict__ Wk,
                        const float* __restrict__ Wq, const float* __restrict__ Wv,
                        const float* __restrict__ Wa) {
    int c = blockIdx.x;
    const float* W; int k0 = 0;
    if (c < 6) {
        int t = c >> 1; k0 = (c & 1) * 128;
        W = Wad + (size_t)t * 256 * 128;
    } else {
        int cc = c - 6;
        int l = cc / 12, rem = cc % 12, g = rem / 3, t = rem % 3;
        const float* Wg = (g == 0) ? Wk : (g == 1) ? Wq : (g == 2) ? Wv : Wa;
        W = Wg + (size_t)l * 3 * 128 * 128 + (size_t)t * 128 * 128;
    }
    __half* oh = d_wpack + (size_t)c * 16384;
    for (int i = threadIdx.x; i < 16384; i += 256) {
        int n = i >> 7, k = i & 127;
        oh[i] = __float2half_rn(W[(size_t)(k0 + k) * 128 + n]);
    }
}

// ---------------- smem layout ----------------------------------------------------
#define SROW   136
#define OFF_A  0
#define OFF_B  34816
#define GSMEM  69632

// ---------------- generic GEMM core (adapt / att) --------------------------------
// GATHER: 1 gather fp32 rows via nperm, 3 contiguous fp16 + GELU
// EPI: 1 tanh->f32(outf), 3 combine1(LN+ReLU->d_h1), 4 combine2(->outfinal via nperm)
template<int GATHER, int EPI>
__device__ __forceinline__ void gemm_core(const void* __restrict__ Av, int nch, int cbase,
                                          const float* __restrict__ bias,
                                          float* __restrict__ outf,
                                          const float* __restrict__ hx,
                                          const float* __restrict__ skip,
                                          const float* __restrict__ gamma,
                                          const float* __restrict__ beta,
                                          float* __restrict__ outfinal) {
    extern __shared__ char smem[];
    const uint32_t sb = smem_u32(smem);
    const int tid = threadIdx.x;
    const int wid = tid >> 5, lane = tid & 31;
    const int base = blockIdx.x * 128;
    const int t = (base >= d_topad[1]) + (base >= d_topad[2]);
    const float* bt = bias + t * 128;
    const int lda = nch * 128;
    const int wm = wid & 3, wn = wid >> 2;

    float acc[2][8][4];
    #pragma unroll
    for (int mi = 0; mi < 2; mi++)
        #pragma unroll
        for (int nj = 0; nj < 8; nj++)
            #pragma unroll
            for (int e = 0; e < 4; e++) acc[mi][nj][e] = 0.f;

    const uint32_t aoff = (uint32_t)((wm*32 + (lane & 15)) * SROW + (lane >> 4) * 8) * 2;
    const int l16 = lane & 15;
    const uint32_t boff = (uint32_t)((wn*64 + (l16 & 7)) * SROW + (l16 >> 3) * 8) * 2;

    for (int kc = 0; kc < nch; kc++) {
        if (kc > 0) __syncthreads();
        {
            int chunk = cbase + t * nch + kc;
            const uint4* bsrc = (const uint4*)(d_wpack + (size_t)chunk * 16384);
            #pragma unroll
            for (int i = 0; i < 8; i++) {
                int idx = tid + i * 256;
                int n = idx >> 4, k8g = idx & 15;
                uint32_t doff = (uint32_t)(n * SROW + k8g * 8) * 2;
                *(uint4*)(smem + OFF_B + doff) = bsrc[idx];
            }
        }
        #pragma unroll
        for (int i = 0; i < 8; i++) {
            int gi = tid + i * 256;
            int row = gi >> 4;
            int k8 = (gi & 15) * 8;
            if (GATHER == 1) {
                const float* A = (const float*)Av;
                float v[8];
                int rn = d_nperm[base + row];
                if (rn >= 0) {
                    const float4* ap = (const float4*)(A + (size_t)rn * lda + kc*128 + k8);
                    float4 a0 = ap[0], a1 = ap[1];
                    v[0]=a0.x; v[1]=a0.y; v[2]=a0.z; v[3]=a0.w;
                    v[4]=a1.x; v[5]=a1.y; v[6]=a1.z; v[7]=a1.w;
                } else {
                    #pragma unroll
                    for (int j = 0; j < 8; j++) v[j] = 0.f;
                }
                union { __half b[8]; uint4 u; } ph;
                #pragma unroll
                for (int j = 0; j < 8; j++) ph.b[j] = __float2half_rn(v[j]);
                *(uint4*)(smem + OFF_A + (uint32_t)(row * SROW + k8) * 2) = ph.u;
            } else {
                const __half* A = (const __half*)Av;
                uint4 raw = *(const uint4*)(A + (size_t)(base + row) * 128 + k8);
                union { __half b[8]; uint4 u; } ph;
                const __half2* hp = reinterpret_cast<const __half2*>(&raw);
                #pragma unroll
                for (int j = 0; j < 4; j++) {
                    float2 f2 = __half22float2(hp[j]);
                    f2.x = 0.5f * f2.x * (1.0f + erff(f2.x * 0.70710678118654752f));
                    f2.y = 0.5f * f2.y * (1.0f + erff(f2.y * 0.70710678118654752f));
                    ph.b[2*j]   = __float2half_rn(f2.x);
                    ph.b[2*j+1] = __float2half_rn(f2.y);
                }
                *(uint4*)(smem + OFF_A + (uint32_t)(row * SROW + k8) * 2) = ph.u;
            }
        }
        __syncthreads();

        #pragma unroll
        for (int ks = 0; ks < 8; ks++) {
            uint32_t ah[2][4];
            #pragma unroll
            for (int mi = 0; mi < 2; mi++) {
                uint32_t ad = sb + aoff + (uint32_t)(mi*16*SROW + ks*16) * 2;
                ldmatrix_x4(ah[mi], ad + OFF_A);
            }
            uint32_t bf[8][2];
            #pragma unroll
            for (int nj = 0; nj < 8; nj++) {
                uint32_t bd = sb + boff + (uint32_t)(nj*8*SROW + ks*16) * 2;
                ldmatrix_x2(bf[nj], bd + OFF_B);
            }
            #pragma unroll
            for (int mi = 0; mi < 2; mi++)
                #pragma unroll
                for (int nj = 0; nj < 8; nj++)
                    mma16816h(acc[mi][nj], ah[mi], bf[nj]);
        }
    }
    __syncthreads();

    float* stage = (float*)smem;              // [128][132]
    #pragma unroll
    for (int mi = 0; mi < 2; mi++) {
        #pragma unroll
        for (int nj = 0; nj < 8; nj++) {
            int row = wm*32 + mi*16 + (lane >> 2);
            int col = wn*64 + nj*8 + 2*(lane & 3);
            float b0 = __ldg(&bt[col]), b1 = __ldg(&bt[col+1]);
            float v0 = acc[mi][nj][0] + b0;
            float v1 = acc[mi][nj][1] + b1;
            float v2 = acc[mi][nj][2] + b0;
            float v3 = acc[mi][nj][3] + b1;
            if (EPI == 1) { v0 = tanhf(v0); v1 = tanhf(v1); v2 = tanhf(v2); v3 = tanhf(v3); }
            stage[row*132 + col]     = v0;
            stage[row*132 + col + 1] = v1;
            stage[(row+8)*132 + col]     = v2;
            stage[(row+8)*132 + col + 1] = v3;
        }
    }
    __syncthreads();

    if (EPI == 1) {
        for (int i = tid; i < 4096; i += 256) {
            int row = i >> 5, c4 = i & 31;
            *(float4*)(outf + ((size_t)(base + row)) * 128 + c4 * 4) =
                *(const float4*)(stage + row * 132 + c4 * 4);
        }
    } else {
        const unsigned full = 0xffffffffu;
        float alpha = 1.0f / (1.0f + __expf(-__ldg(&skip[t])));
        float ia = 1.0f - alpha;
        float4 g4, b4;
        if (EPI == 3) {
            g4 = *(const float4*)(gamma + t*128 + lane*4);
            b4 = *(const float4*)(beta  + t*128 + lane*4);
        }
        #pragma unroll
        for (int i = 0; i < 16; i++) {
            int row = wid*16 + i;
            float4 tr = *(const float4*)(stage + row*132 + lane*4);
            float4 hx4 = *(const float4*)(hx + (size_t)(base+row)*128 + lane*4);
            float4 o;
            o.x = tr.x*alpha + hx4.x*ia;
            o.y = tr.y*alpha + hx4.y*ia;
            o.z = tr.z*alpha + hx4.z*ia;
            o.w = tr.w*alpha + hx4.w*ia;
            if (EPI == 3) {
                float sm = o.x + o.y + o.z + o.w;
                float sq = o.x*o.x + o.y*o.y + o.z*o.z + o.w*o.w;
                #pragma unroll
                for (int d = 16; d; d >>= 1) {
                    sm += __shfl_xor_sync(full, sm, d);
                    sq += __shfl_xor_sync(full, sq, d);
                }
                float mean = sm * (1.0f/128.0f);
                float var  = sq * (1.0f/128.0f) - mean*mean;
                float rstd = rsqrtf(var + 1e-5f);
                float4 y;
                y.x = fmaxf((o.x-mean)*rstd*g4.x + b4.x, 0.f);
                y.y = fmaxf((o.y-mean)*rstd*g4.y + b4.y, 0.f);
                y.z = fmaxf((o.z-mean)*rstd*g4.z + b4.z, 0.f);
                y.w = fmaxf((o.w-mean)*rstd*g4.w + b4.w, 0.f);
                *(float4*)(d_h1 + (size_t)(base+row)*128 + lane*4) = y;
            } else {
                int node = d_nperm[base + row];
                if (node >= 0)
                    *(float4*)(outfinal + (size_t)node*128 + lane*4) = o;
            }
        }
    }
}

__global__ void __launch_bounds__(256,2)
k_gemm_adapt(const float* __restrict__ x, const float* __restrict__ bad) {
    gemm_core<1,1>(x, 2, 0, bad, d_h0, nullptr, nullptr, nullptr, nullptr, nullptr);
}
__global__ void __launch_bounds__(256,2)
k_gemm_att0(int cb, const float* __restrict__ ba, const float* __restrict__ skip,
            const float* __restrict__ gamma, const float* __restrict__ beta) {
    gemm_core<3,3>(d_aggh, 1, cb, ba, nullptr, d_h0, skip, gamma, beta, nullptr);
}
__global__ void __launch_bounds__(256,2)
k_gemm_att1(int cb, const float* __restrict__ ba, const float* __restrict__ skip,
            float* __restrict__ out) {
    gemm_core<3,4>(d_aggh, 1, cb, ba, nullptr, d_h1, skip, nullptr, nullptr, out);
}

// ---------------- fused k/q/v GEMM: A staged ONCE, loop over 3 B's --------------
__global__ void __launch_bounds__(256,2)
k_gemm_kqv(int l, const float* __restrict__ bk, const float* __restrict__ bq,
           const float* __restrict__ bv) {
    extern __shared__ char smem[];
    const uint32_t sb = smem_u32(smem);
    const int tid = threadIdx.x;
    const int wid = tid >> 5, lane = tid & 31;
    const int base = blockIdx.x * 128;
    const int t = (base >= d_topad[1]) + (base >= d_topad[2]);
    const float* A = l ? d_h1 : d_h0;
    const int lbase = 6 + l*12;
    const int wm = wid & 3, wn = wid >> 2;

    // stage A (fp32 -> fp16) once
    #pragma unroll
    for (int i = 0; i < 8; i++) {
        int gi = tid + i * 256;
        int row = gi >> 4;
        int k8 = (gi & 15) * 8;
        const float4* ap = (const float4*)(A + (size_t)(base + row) * 128 + k8);
        float4 a0 = ap[0], a1 = ap[1];
        union { __half b[8]; uint4 u; } ph;
        ph.b[0]=__float2half_rn(a0.x); ph.b[1]=__float2half_rn(a0.y);
        ph.b[2]=__float2half_rn(a0.z); ph.b[3]=__float2half_rn(a0.w);
        ph.b[4]=__float2half_rn(a1.x); ph.b[5]=__float2half_rn(a1.y);
        ph.b[6]=__float2half_rn(a1.z); ph.b[7]=__float2half_rn(a1.w);
        *(uint4*)(smem + OFF_A + (uint32_t)(row * SROW + k8) * 2) = ph.u;
    }

    const uint32_t aoff = (uint32_t)((wm*32 + (lane & 15)) * SROW + (lane >> 4) * 8) * 2;
    const int l16 = lane & 15;
    const uint32_t boff = (uint32_t)((wn*64 + (l16 & 7)) * SROW + (l16 >> 3) * 8) * 2;

    for (int s = 0; s < 3; s++) {
        __syncthreads();   // A staged / previous epilogue stage reads done
        int chunk = lbase + s*3 + t;
        {
            const uint4* bsrc = (const uint4*)(d_wpack + (size_t)chunk * 16384);
            #pragma unroll
            for (int i = 0; i < 8; i++) {
                int idx = tid + i * 256;
                int n = idx >> 4, k8g = idx & 15;
                *(uint4*)(smem + OFF_B + (uint32_t)(n * SROW + k8g * 8) * 2) = bsrc[idx];
            }
        }
        __syncthreads();

        float acc[2][8][4];
        #pragma unroll
        for (int mi = 0; mi < 2; mi++)
            #pragma unroll
            for (int nj = 0; nj < 8; nj++)
                #pragma unroll
                for (int e = 0; e < 4; e++) acc[mi][nj][e] = 0.f;

        #pragma unroll
        for (int ks = 0; ks < 8; ks++) {
            uint32_t ah[2][4];
            #pragma unroll
            for (int mi = 0; mi < 2; mi++) {
                uint32_t ad = sb + aoff + (uint32_t)(mi*16*SROW + ks*16) * 2;
                ldmatrix_x4(ah[mi], ad + OFF_A);
            }
            uint32_t bf[8][2];
            #pragma unroll
            for (int nj = 0; nj < 8; nj++) {
                uint32_t bd = sb + boff + (uint32_t)(nj*8*SROW + ks*16) * 2;
                ldmatrix_x2(bf[nj], bd + OFF_B);
            }
            #pragma unroll
            for (int mi = 0; mi < 2; mi++)
                #pragma unroll
                for (int nj = 0; nj < 8; nj++)
                    mma16816h(acc[mi][nj], ah[mi], bf[nj]);
        }
        __syncthreads();   // B reads done; reuse B region as fp16 stage

        const float* bsel = (s == 0) ? bk : (s == 1) ? bq : bv;
        const float* bt = bsel + l*TT*HIDD + t*128;
        __half* hstage = (__half*)(smem + OFF_B);
        #pragma unroll
        for (int mi = 0; mi < 2; mi++) {
            #pragma unroll
            for (int nj = 0; nj < 8; nj++) {
                int row = wm*32 + mi*16 + (lane >> 2);
                int col = wn*64 + nj*8 + 2*(lane & 3);
                float b0 = __ldg(&bt[col]), b1 = __ldg(&bt[col+1]);
                __half2 h01 = __floats2half2_rn(acc[mi][nj][0] + b0, acc[mi][nj][1] + b1);
                __half2 h23 = __floats2half2_rn(acc[mi][nj][2] + b0, acc[mi][nj][3] + b1);
                *(__half2*)(hstage + row * SROW + col)     = h01;
                *(__half2*)(hstage + (row+8) * SROW + col) = h23;
            }
        }
        __syncthreads();

        __half* dst = (s == 0) ? d_kh : (s == 1) ? d_qh : d_vh;
        dst += (size_t)base * 128;
        #pragma unroll
        for (int i = 0; i < 8; i++) {
            int idx = tid + i * 256;
            int row = idx >> 4, seg = idx & 15;
            uint4 v = *(const uint4*)(hstage + row * SROW + seg * 8);
            *(uint4*)(dst + (size_t)row * 128 + seg * 8) = v;
        }
    }
}

// ---------------- per-node relation transforms (fp16 in/out, FFMA) -------------
__global__ void k_reltrans(const float* __restrict__ Ratt, const float* __restrict__ Rmsg,
                           const float* __restrict__ pri) {
    const int slot = blockIdx.y;
    const int r = slot >> 1;
    const bool isV = slot & 1;
    const __half* srcv = isV ? d_vh : d_kh;
    const float* Wh = (isV ? Rmsg : Ratt) + r*HH*DKK*DKK;

    const int lane = threadIdx.x & 31;
    const int wid  = threadIdx.x >> 5;
    const int h = lane >> 2;
    const int f0 = (lane & 3) * 4;
    const float* Wp = Wh + h*256;
    const float pscale = isV ? 1.0f : (__ldg(&pri[r*HH + h]) * 0.25f);

    float4 w[16];
    #pragma unroll
    for (int d = 0; d < 16; d++) w[d] = *(const float4*)(Wp + d*16 + f0);

    const int wpb = blockDim.x >> 5;
    for (int n = blockIdx.x*wpb + wid; n < NP; n += gridDim.x*wpb) {
        uint4 raw0 = *(const uint4*)(srcv + (size_t)n*128 + h*16);
        uint4 raw1 = *(const uint4*)(srcv + (size_t)n*128 + h*16 + 8);
        float f[16];
        {
            const __half2* hp0 = reinterpret_cast<const __half2*>(&raw0);
            const __half2* hp1 = reinterpret_cast<const __half2*>(&raw1);
            #pragma unroll
            for (int j = 0; j < 4; j++) {
                float2 t2 = __half22float2(hp0[j]);
                f[2*j] = t2.x; f[2*j+1] = t2.y;
                float2 u2 = __half22float2(hp1[j]);
                f[8+2*j] = u2.x; f[8+2*j+1] = u2.y;
            }
        }
        float4 acc = make_float4(0.f,0.f,0.f,0.f);
        #pragma unroll
        for (int d = 0; d < 16; d++) {
            acc.x = fmaf(f[d], w[d].x, acc.x);
            acc.y = fmaf(f[d], w[d].y, acc.y);
            acc.z = fmaf(f[d], w[d].z, acc.z);
            acc.w = fmaf(f[d], w[d].w, acc.w);
        }
        if (!isV) { acc.x *= pscale; acc.y *= pscale; acc.z *= pscale; acc.w *= pscale; }
        *(uint2*)(d_kvrel + ((size_t)n*RR + r)*256 + (isV ? 128 : 0) + h*16 + f0) = f4_to_h4(acc);
    }
}

// ---------------- edge phase: warp-per-dst, online softmax ---------------------
__device__ __forceinline__ void edge_step(uint2 kr, uint2 vr, const float4 q4,
                                          float& m, float& s, float4& acc) {
    const unsigned full = 0xffffffffu;
    float4 k4 = h4_to_f4(kr);
    float4 v4 = h4_to_f4(vr);
    float p = q4.x*k4.x + q4.y*k4.y + q4.z*k4.z + q4.w*k4.w;
    p += __shfl_xor_sync(full, p, 1);
    p += __shfl_xor_sync(full, p, 2);
    float mn = fmaxf(m, p);
    float corr = __expf(m - mn);
    float w = __expf(p - mn);
    s = s*corr + w;
    acc.x = fmaf(w, v4.x, acc.x*corr);
    acc.y = fmaf(w, v4.y, acc.y*corr);
    acc.z = fmaf(w, v4.z, acc.z*corr);
    acc.w = fmaf(w, v4.w, acc.w*corr);
    m = mn;
}

__global__ void k_edge() {
    const int n = (blockIdx.x*blockDim.x + threadIdx.x) >> 5;
    if (n >= NN) return;
    const int lane = threadIdx.x & 31;

    const int ip = d_iperm[n];
    float4 q4 = h4_to_f4(*(const uint2*)(d_qh + (size_t)ip*128 + lane*4));
    const int beg = d_off[n], end = d_off[n+1];

    float m = -1e30f, s = 0.f;
    float4 acc = make_float4(0.f,0.f,0.f,0.f);

    int e = beg;
    for (; e + 1 < end; e += 2) {
        int pk0 = d_epack[e], pk1 = d_epack[e+1];
        const __half* b0 = d_kvrel + (size_t)pk0*256;
        const __half* b1 = d_kvrel + (size_t)pk1*256;
        uint2 k0 = *(const uint2*)(b0 + lane*4);
        uint2 v0 = *(const uint2*)(b0 + 128 + lane*4);
        uint2 k1 = *(const uint2*)(b1 + lane*4);
        uint2 v1 = *(const uint2*)(b1 + 128 + lane*4);
        edge_step(k0, v0, q4, m, s, acc);
        edge_step(k1, v1, q4, m, s, acc);
    }
    if (e < end) {
        int pk0 = d_epack[e];
        const __half* b0 = d_kvrel + (size_t)pk0*256;
        uint2 k0 = *(const uint2*)(b0 + lane*4);
        uint2 v0 = *(const uint2*)(b0 + 128 + lane*4);
        edge_step(k0, v0, q4, m, s, acc);
    }
    float inv = 1.0f / fmaxf(s, 1e-9f);
    acc.x *= inv; acc.y *= inv; acc.z *= inv; acc.w *= inv;
    *(uint2*)(d_aggh + (size_t)ip*128 + lane*4) = f4_to_h4(acc);
}

// ---------------- launch --------------------------------------------------------
extern "C" void kernel_launch(void* const* d_in, const int* in_sizes, int n_in,
                              void* d_out, int out_size) {
    const float* x      = (const float*)d_in[0];
    const int*   ntypes = (const int*)d_in[1];
    const int*   ei     = (const int*)d_in[2];
    const int*   et     = (const int*)d_in[3];
    const float* Wad    = (const float*)d_in[4];
    const float* bad    = (const float*)d_in[5];
    const float* Wk     = (const float*)d_in[6];
    const float* bk     = (const float*)d_in[7];
    const float* Wq     = (const float*)d_in[8];
    const float* bq     = (const float*)d_in[9];
    const float* Wv     = (const float*)d_in[10];
    const float* bv     = (const float*)d_in[11];
    const float* Wa     = (const float*)d_in[12];
    const float* ba     = (const float*)d_in[13];
    const float* pri    = (const float*)d_in[14];
    const float* ratt   = (const float*)d_in[15];
    const float* rmsg   = (const float*)d_in[16];
    const float* skip   = (const float*)d_in[17];
    const float* gamma  = (const float*)d_in[18];
    const float* beta   = (const float*)d_in[19];
    float* out = (float*)d_out;

    const int* srcA = ei;
    const int* dstA = ei + EE;

    cudaFuncSetAttribute(k_gemm_adapt, cudaFuncAttributeMaxDynamicSharedMemorySize, GSMEM);
    cudaFuncSetAttribute(k_gemm_kqv,   cudaFuncAttributeMaxDynamicSharedMemorySize, GSMEM);
    cudaFuncSetAttribute(k_gemm_att0,  cudaFuncAttributeMaxDynamicSharedMemorySize, GSMEM);
    cudaFuncSetAttribute(k_gemm_att1,  cudaFuncAttributeMaxDynamicSharedMemorySize, GSMEM);

    const int SCAN_BLK = (NN + 255) / 256;
    const int WARP_BLK = (NN*32 + 255) / 256;

    k_init<<<(NP+255)/256, 256>>>();
    k_count<<<(EE+255)/256, 256>>>(ntypes, dstA);
    k_toffsets<<<1, 1>>>();
    k_scatter_nodes<<<(NN+255)/256, 256>>>(ntypes);
    k_scan1<<<SCAN_BLK, 256>>>();
    k_scan2<<<1, 256>>>(SCAN_BLK);
    k_scan3<<<SCAN_BLK, 256>>>();
    k_scatter_edges<<<(EE+255)/256, 256>>>(srcA, dstA, et);
    k_wprep<<<NCHUNKS, 256>>>(Wad, Wk, Wq, Wv, Wa);

    k_gemm_adapt<<<NTILE, 256, GSMEM>>>(x, bad);

    const int LP = RR*HH;
    const int LR = RR*HH*DKK*DKK;

    for (int l = 0; l < 2; l++) {
        int lbase = 6 + l*12;
        k_gemm_kqv<<<NTILE, 256, GSMEM>>>(l, bk, bq, bv);
        k_reltrans<<<dim3(296, 8), 256>>>(ratt + (size_t)l*LR, rmsg + (size_t)l*LR, pri + l*LP);
        k_edge<<<WARP_BLK, 256>>>();
        if (l == 0) {
            k_gemm_att0<<<NTILE, 256, GSMEM>>>(lbase + 9, ba + l*TT*HIDD, skip + l*TT, gamma, beta);
        } else {
            k_gemm_att1<<<NTILE, 256, GSMEM>>>(lbase + 9, ba + l*TT*HIDD, skip + l*TT, out);
        }
    }
}